// round 5
// baseline (speedup 1.0000x reference)
#include <cuda_runtime.h>
#include <cstdint>

#define BB 8
#define GSZ 512
#define CC 32

// ---------------- scratch (device globals; no runtime allocation) ----------
// RULE (bug found in R1-R3): these symbols are referenced ONLY inside device
// code. Passing them as kernel arguments from host passes the host shadow
// address, which ATS happily dereferences into host RAM => silent zeros.
__device__ __align__(16) unsigned long long g_scat[BB * GSZ * GSZ];
__device__ __align__(16) float g_grid[BB * GSZ * GSZ];
__device__ __align__(16) unsigned char g_m1[BB * GSZ * GSZ];
__device__ __align__(16) unsigned char g_m2[BB * 256 * 256];
__device__ __align__(16) unsigned char g_m3[BB * 128 * 128];
__device__ __align__(16) unsigned char g_m4[BB * 64 * 64];
__device__ __align__(16) float g_y1[(size_t)BB * GSZ * GSZ * CC];
__device__ __align__(16) float g_y2[(size_t)BB * 256 * 256 * CC];
__device__ __align__(16) float g_y3[(size_t)BB * 128 * 128 * CC];
__device__ __align__(16) float g_y4[(size_t)BB * 64 * 64 * CC];

// ---------------- reset ----------------
__global__ void k_reset() {
    int n = BB * GSZ * GSZ;
    for (int i = blockIdx.x * blockDim.x + threadIdx.x; i < n; i += gridDim.x * blockDim.x)
        g_scat[i] = 0ULL;
}

// ---------------- scatter: first-write-wins via packed (~idx, bits) --------
__global__ void k_scatter(const int* __restrict__ coords, const float* __restrict__ feats, int n) {
    int i = blockIdx.x * blockDim.x + threadIdx.x;
    if (i >= n) return;
    int b = coords[3 * i + 0];
    int y = coords[3 * i + 1];
    int x = coords[3 * i + 2];
    unsigned long long v = ((unsigned long long)(~(unsigned)i) << 32) |
                           (unsigned long long)__float_as_uint(feats[i]);
    atomicMax(&g_scat[((size_t)b * GSZ + y) * GSZ + x], v);
}

// ---------------- decode packed -> grid + m1 ----------------
__global__ void k_decode() {
    int n = BB * GSZ * GSZ;
    for (int i = blockIdx.x * blockDim.x + threadIdx.x; i < n; i += gridDim.x * blockDim.x) {
        unsigned long long v = g_scat[i];
        g_m1[i] = v ? (unsigned char)1 : (unsigned char)0;
        g_grid[i] = v ? __uint_as_float((unsigned)v) : 0.0f;
    }
}

// ---------------- 2x2 max-pool of mask (globals referenced in-device) ------
template <int L>
__global__ void k_maskdown() {
    const unsigned char* mi = (L == 0) ? g_m1 : (L == 1) ? g_m2 : g_m3;
    unsigned char* mo = (L == 0) ? g_m2 : (L == 1) ? g_m3 : g_m4;
    const int Hout = (L == 0) ? 256 : (L == 1) ? 128 : 64;
    const int Hin = Hout * 2;

    int tot = BB * Hout * Hout;
    int i = blockIdx.x * blockDim.x + threadIdx.x;
    if (i >= tot) return;
    int x = i % Hout;
    int y = (i / Hout) % Hout;
    int b = i / (Hout * Hout);
    const unsigned char* p = mi + ((size_t)b * Hin + 2 * y) * Hin + 2 * x;
    mo[i] = (unsigned char)(p[0] | p[1] | p[Hin] | p[Hin + 1]);
}

// ---------------- DENSE conv1: 5x5 s1 pad2, 1->32 ch -----------------------
__global__ void k_conv1_dense(const float* __restrict__ K1) {
    __shared__ float in_s[12 * 20];       // (8+4) rows x (16+4) cols
    __shared__ unsigned char m_s[8 * 16];

    int tid = threadIdx.x;
    int b = blockIdx.z;
    int ox0 = blockIdx.x * 16;
    int oy0 = blockIdx.y * 8;
    int co = tid & 31;
    int py = tid >> 5;

    float w[25];
#pragma unroll
    for (int t = 0; t < 25; t++) w[t] = __ldg(&K1[t * 32 + co]);

    for (int p = tid; p < 240; p += 256) {
        int r = p / 20;
        int c = p - r * 20;
        int gy = oy0 + r - 2;
        int gx = ox0 + c - 2;
        float v = 0.0f;
        if ((unsigned)gy < (unsigned)GSZ && (unsigned)gx < (unsigned)GSZ)
            v = g_grid[((size_t)b * GSZ + gy) * GSZ + gx];
        in_s[p] = v;
    }
    for (int p = tid; p < 128; p += 256) {
        int r = p >> 4;
        int c = p & 15;
        m_s[p] = g_m1[((size_t)b * GSZ + oy0 + r) * GSZ + ox0 + c];
    }
    __syncthreads();

    float* orow = g_y1 + (((size_t)b * GSZ + oy0 + py) * GSZ + ox0) * 32 + co;
#pragma unroll
    for (int px = 0; px < 16; px++) {
        float acc = 0.0f;
#pragma unroll
        for (int t = 0; t < 25; t++) {
            int dy = t / 5;
            int dx = t - dy * 5;
            acc = fmaf(in_s[(py + dy) * 20 + px + dx], w[t], acc);
        }
        orow[px * 32] = m_s[py * 16 + px] ? fmaxf(acc, 0.0f) : 0.0f;
    }
}

// ---------------- DENSE 3x3 stride-2 pad-1 conv, 32->32 ch -----------------
// Template level L selects the global buffers INSIDE device code.
// Tile: 8(y) x 4(x) output pixels x 16 out-channels (blockIdx.z & 1 = half).
template <int L>
__global__ void k_conv_s2s(const float* __restrict__ Kw) {
    const float* in = (L == 0) ? g_y1 : (L == 1) ? g_y2 : g_y3;
    float* out = (L == 0) ? g_y2 : (L == 1) ? g_y3 : g_y4;
    const unsigned char* mo = (L == 0) ? g_m2 : (L == 1) ? g_m3 : g_m4;
    const int Hin = (L == 0) ? 512 : (L == 1) ? 256 : 128;
    const int Hout = Hin / 2;

    __shared__ float in_s[153 * 36];   // 17 rows x 9 cols, 32 ch padded to 36
    __shared__ float w_s[9 * 16 * 36]; // [tap][co16][ci], ci padded to 36

    int tid = threadIdx.x;
    int bz = blockIdx.z;
    int b = bz >> 1;
    int h = bz & 1;
    int ox0 = blockIdx.x * 4;
    int oy0 = blockIdx.y * 8;
    int ix0 = 2 * ox0 - 1;
    int iy0 = 2 * oy0 - 1;

    for (int idx = tid; idx < 4608; idx += 256) {   // 9*32*16
        int t = idx / 512;
        int rem = idx - t * 512;
        int ci = rem >> 4;
        int c16 = rem & 15;
        w_s[(t * 16 + c16) * 36 + ci] = Kw[(t * 32 + ci) * 32 + h * 16 + c16];
    }
    for (int idx = tid; idx < 1224; idx += 256) {   // 153 cells * 8 quarters
        int cell = idx >> 3;
        int q = idx & 7;
        int r = cell / 9;
        int c = cell - r * 9;
        int gy = iy0 + r;
        int gx = ix0 + c;
        float4 v = make_float4(0.0f, 0.0f, 0.0f, 0.0f);
        if ((unsigned)gy < (unsigned)Hin && (unsigned)gx < (unsigned)Hin)
            v = ((const float4*)(in + (((size_t)b * Hin + gy) * Hin + gx) * 32))[q];
        ((float4*)(in_s + cell * 36))[q] = v;
    }
    __syncthreads();

    int py = tid >> 5;
    int lane = tid & 31;
    int c16 = lane & 15;
    int pxh = lane >> 4;

    float acc0 = 0.0f, acc1 = 0.0f;
#pragma unroll
    for (int t = 0; t < 9; t++) {
        int dy = t / 3;
        int dx = t - dy * 3;
        int row = 2 * py + dy;
        float4 wq[8];
        const float4* wv = (const float4*)(w_s + (t * 16 + c16) * 36);
#pragma unroll
        for (int qq = 0; qq < 8; qq++) wq[qq] = wv[qq];

        int px0 = pxh * 2;
        const float4* ip0 = (const float4*)(in_s + (row * 9 + 2 * px0 + dx) * 36);
        const float4* ip1 = (const float4*)(in_s + (row * 9 + 2 * px0 + 2 + dx) * 36);
#pragma unroll
        for (int qq = 0; qq < 8; qq++) {
            float4 a0 = ip0[qq];
            float4 a1 = ip1[qq];
            acc0 = fmaf(a0.x, wq[qq].x, acc0);
            acc0 = fmaf(a0.y, wq[qq].y, acc0);
            acc0 = fmaf(a0.z, wq[qq].z, acc0);
            acc0 = fmaf(a0.w, wq[qq].w, acc0);
            acc1 = fmaf(a1.x, wq[qq].x, acc1);
            acc1 = fmaf(a1.y, wq[qq].y, acc1);
            acc1 = fmaf(a1.z, wq[qq].z, acc1);
            acc1 = fmaf(a1.w, wq[qq].w, acc1);
        }
    }

    int oy = oy0 + py;
    int px0 = pxh * 2;
    {
        int ox = ox0 + px0;
        unsigned char m = mo[((size_t)b * Hout + oy) * Hout + ox];
        out[(((size_t)b * Hout + oy) * Hout + ox) * 32 + h * 16 + c16] =
            m ? fmaxf(acc0, 0.0f) : 0.0f;
    }
    {
        int ox = ox0 + px0 + 1;
        unsigned char m = mo[((size_t)b * Hout + oy) * Hout + ox];
        out[(((size_t)b * Hout + oy) * Hout + ox) * 32 + h * 16 + c16] =
            m ? fmaxf(acc1, 0.0f) : 0.0f;
    }
}

// ---------------- masked global pool + MLP head ----------------
__global__ void k_final(
    const float* __restrict__ x2,
    const float* __restrict__ W1, const float* __restrict__ b1,
    const float* __restrict__ W2, const float* __restrict__ b2,
    const float* __restrict__ W3, const float* __restrict__ b3,
    float* __restrict__ out)
{
    __shared__ float s_pool[8][32];
    __shared__ int s_cnt[8];
    __shared__ float s_z[64];
    __shared__ float s_t1[64];

    int b = blockIdx.x;
    int tid = threadIdx.x;
    int wg = tid >> 5;
    int lane = tid & 31;

    float ps = 0.0f;
    int pc = 0;
    const float* y4b = g_y4 + (size_t)b * 4096 * 32;
    const unsigned char* m4b = g_m4 + (size_t)b * 4096;
    for (int p = wg; p < 4096; p += 8) {
        ps += y4b[(size_t)p * 32 + lane];        // dense: inactive cells are 0
        if (m4b[p]) pc++;
    }
    s_pool[wg][lane] = ps;
    if (lane == 0) s_cnt[wg] = pc;
    __syncthreads();

    if (tid < 32) {
        float s = 0.0f;
        int c = 0;
#pragma unroll
        for (int w = 0; w < 8; w++) { s += s_pool[w][tid]; c += s_cnt[w]; }
        s_z[tid] = s / fmaxf((float)c, 1.0f);
    }
    if (tid < 64) {
        float a = b1[tid];
        a = fmaf(x2[b * 3 + 0], W1[0 * 64 + tid], a);
        a = fmaf(x2[b * 3 + 1], W1[1 * 64 + tid], a);
        a = fmaf(x2[b * 3 + 2], W1[2 * 64 + tid], a);
        s_t1[tid] = fmaxf(a, 0.0f);
    }
    __syncthreads();
    if (tid < 32) {
        float a = b2[tid];
#pragma unroll
        for (int k = 0; k < 64; k++) a = fmaf(s_t1[k], W2[k * 32 + tid], a);
        s_z[32 + tid] = a;
    }
    __syncthreads();
    if (tid < 128) {
        float a = b3[tid];
#pragma unroll
        for (int k = 0; k < 64; k++) a = fmaf(s_z[k], W3[k * 128 + tid], a);
        out[b * 128 + tid] = fmaxf(a, 0.0f);
    }
}

// ---------------- launch: pure kernel launches; no g_* symbol as argument --
extern "C" void kernel_launch(void* const* d_in, const int* in_sizes, int n_in,
                              void* d_out, int out_size) {
    const int* coords = (const int*)d_in[0];
    const float* feats = (const float*)d_in[1];
    const float* x2 = (const float*)d_in[2];
    const float* K1 = (const float*)d_in[3];
    const float* K2 = (const float*)d_in[4];
    const float* K3 = (const float*)d_in[5];
    const float* K4 = (const float*)d_in[6];
    const float* W1 = (const float*)d_in[7];
    const float* b1 = (const float*)d_in[8];
    const float* W2 = (const float*)d_in[9];
    const float* b2 = (const float*)d_in[10];
    const float* W3 = (const float*)d_in[11];
    const float* b3 = (const float*)d_in[12];
    float* out = (float*)d_out;

    int npts = in_sizes[0] / 3;  // 262144

    k_reset<<<2048, 256>>>();
    k_scatter<<<(npts + 255) / 256, 256>>>(coords, feats, npts);
    k_decode<<<4096, 256>>>();
    k_maskdown<0><<<(BB * 256 * 256) / 256, 256>>>();
    k_maskdown<1><<<(BB * 128 * 128) / 256, 256>>>();
    k_maskdown<2><<<(BB * 64 * 64) / 256, 256>>>();
    k_conv1_dense<<<dim3(32, 64, BB), 256>>>(K1);
    k_conv_s2s<0><<<dim3(64, 32, 2 * BB), 256>>>(K2);
    k_conv_s2s<1><<<dim3(32, 16, 2 * BB), 256>>>(K3);
    k_conv_s2s<2><<<dim3(16, 8, 2 * BB), 256>>>(K4);
    k_final<<<BB, 256>>>(x2, W1, b1, W2, b2, W3, b3, out);
}

// round 6
// speedup vs baseline: 2.1493x; 2.1493x over previous
#include <cuda_runtime.h>
#include <cstdint>

#define BB 8
#define GSZ 512
#define CC 32

// RULE: g_* symbols are referenced ONLY inside device code (host-shadow bug, R1-R4).
__device__ __align__(16) unsigned long long g_scat[BB * GSZ * GSZ];
__device__ __align__(16) float g_grid[BB * GSZ * GSZ];
__device__ __align__(16) unsigned char g_m1[BB * GSZ * GSZ];
__device__ __align__(16) unsigned char g_m2[BB * 256 * 256];
__device__ __align__(16) unsigned char g_m3[BB * 128 * 128];
__device__ __align__(16) unsigned char g_m4[BB * 64 * 64];
__device__ __align__(16) float g_y1[(size_t)BB * GSZ * GSZ * CC];
__device__ __align__(16) float g_y2[(size_t)BB * 256 * 256 * CC];
__device__ __align__(16) float g_y3[(size_t)BB * 128 * 128 * CC];
__device__ __align__(16) float g_y4[(size_t)BB * 64 * 64 * CC];

// ---------------- reset ----------------
__global__ void k_reset() {
    int n = BB * GSZ * GSZ;
    for (int i = blockIdx.x * blockDim.x + threadIdx.x; i < n; i += gridDim.x * blockDim.x)
        g_scat[i] = 0ULL;
}

// ---------------- scatter: LAST-write-wins via packed (i+1, bits) ----------
__global__ void k_scatter(const int* __restrict__ coords, const float* __restrict__ feats, int n) {
    int i = blockIdx.x * blockDim.x + threadIdx.x;
    if (i >= n) return;
    int b = coords[3 * i + 0];
    int y = coords[3 * i + 1];
    int x = coords[3 * i + 2];
    unsigned long long v = ((unsigned long long)(unsigned)(i + 1) << 32) |
                           (unsigned long long)__float_as_uint(feats[i]);
    atomicMax(&g_scat[((size_t)b * GSZ + y) * GSZ + x], v);
}

// ---------------- decode packed -> grid + m1 ----------------
__global__ void k_decode() {
    int n = BB * GSZ * GSZ;
    for (int i = blockIdx.x * blockDim.x + threadIdx.x; i < n; i += gridDim.x * blockDim.x) {
        unsigned long long v = g_scat[i];
        g_m1[i] = v ? (unsigned char)1 : (unsigned char)0;
        g_grid[i] = v ? __uint_as_float((unsigned)v) : 0.0f;
    }
}

// ---------------- 2x2 max-pool of mask ----------------
template <int L>
__global__ void k_maskdown() {
    const unsigned char* mi = (L == 0) ? g_m1 : (L == 1) ? g_m2 : g_m3;
    unsigned char* mo = (L == 0) ? g_m2 : (L == 1) ? g_m3 : g_m4;
    const int Hout = (L == 0) ? 256 : (L == 1) ? 128 : 64;
    const int Hin = Hout * 2;

    int tot = BB * Hout * Hout;
    int i = blockIdx.x * blockDim.x + threadIdx.x;
    if (i >= tot) return;
    int x = i % Hout;
    int y = (i / Hout) % Hout;
    int b = i / (Hout * Hout);
    const unsigned char* p = mi + ((size_t)b * Hin + 2 * y) * Hin + 2 * x;
    mo[i] = (unsigned char)(p[0] | p[1] | p[Hin] | p[Hin + 1]);
}

// ---------------- SPARSE conv1: 5x5 s1 pad2, 1->32 ch ----------------------
// Tile 16(x) x 8(y). Warp = output row, lane = co. Ballot skips inactive px.
__global__ void k_conv1(const float* __restrict__ K1) {
    __shared__ float in_s[12 * 20];       // (8+4) rows x (16+4) cols
    __shared__ unsigned char m_s[8 * 16];

    int tid = threadIdx.x;
    int b = blockIdx.z;
    int ox0 = blockIdx.x * 16;
    int oy0 = blockIdx.y * 8;
    int co = tid & 31;
    int py = tid >> 5;

    float w[25];
#pragma unroll
    for (int t = 0; t < 25; t++) w[t] = __ldg(&K1[t * 32 + co]);

    for (int p = tid; p < 240; p += 256) {
        int r = p / 20;
        int c = p - r * 20;
        int gy = oy0 + r - 2;
        int gx = ox0 + c - 2;
        float v = 0.0f;
        if ((unsigned)gy < (unsigned)GSZ && (unsigned)gx < (unsigned)GSZ)
            v = g_grid[((size_t)b * GSZ + gy) * GSZ + gx];
        in_s[p] = v;
    }
    for (int p = tid; p < 128; p += 256) {
        m_s[p] = g_m1[((size_t)b * GSZ + oy0 + (p >> 4)) * GSZ + ox0 + (p & 15)];
    }
    __syncthreads();

    unsigned bm = __ballot_sync(0xFFFFFFFFu, (co < 16) && m_s[py * 16 + co]);
    float* orow = g_y1 + (((size_t)b * GSZ + oy0 + py) * GSZ + ox0) * 32 + co;
    while (bm) {
        int px = __ffs(bm) - 1;
        bm &= bm - 1;
        float acc = 0.0f;
#pragma unroll
        for (int t = 0; t < 25; t++) {
            int dy = t / 5;
            int dx = t - dy * 5;
            acc = fmaf(in_s[(py + dy) * 20 + px + dx], w[t], acc);
        }
        orow[px * 32] = fmaxf(acc, 0.0f);
    }
}

// ---------------- SPARSE 3x3 stride-2 pad-1 conv, 32->32 ch ----------------
// Tile 16(x) x 8(y) outputs; 256 threads; warp = output row, lane = co.
// Dyn shared: input window 17x33x32 f32 + weights [9][32][36] f32 + mask.
#define CONV_INS 17952                       // 17*33*32
#define CONV_WS 10368                        // 9*32*36
#define CONV_SMEM ((CONV_INS + CONV_WS) * 4 + 17 * 34 + 64)

template <int L>
__global__ void k_conv_s2(const float* __restrict__ Kw) {
    const float* in = (L == 0) ? g_y1 : (L == 1) ? g_y2 : g_y3;
    float* out = (L == 0) ? g_y2 : (L == 1) ? g_y3 : g_y4;
    const unsigned char* mi = (L == 0) ? g_m1 : (L == 1) ? g_m2 : g_m3;
    const unsigned char* mo = (L == 0) ? g_m2 : (L == 1) ? g_m3 : g_m4;
    const int Hin = (L == 0) ? 512 : (L == 1) ? 256 : 128;
    const int Hout = Hin / 2;

    extern __shared__ float smem[];
    float* in_s = smem;
    float* w_s = smem + CONV_INS;
    unsigned char* m_s = (unsigned char*)(smem + CONV_INS + CONV_WS);

    int tid = threadIdx.x;
    int b = blockIdx.z;
    int ox0 = blockIdx.x * 16;
    int oy0 = blockIdx.y * 8;
    int ix0 = 2 * ox0 - 1;
    int iy0 = 2 * oy0 - 1;

    // weights: float4 over co; w_s[tap][co][ci] padded 36
    for (int i4 = tid; i4 < 2304; i4 += 256) {      // 9*32*8
        int t = i4 >> 8;
        int rem = i4 & 255;
        int ci = rem >> 3;
        int co4 = (rem & 7) * 4;
        float4 wv = __ldg((const float4*)Kw + i4);
        w_s[(t * 32 + co4 + 0) * 36 + ci] = wv.x;
        w_s[(t * 32 + co4 + 1) * 36 + ci] = wv.y;
        w_s[(t * 32 + co4 + 2) * 36 + ci] = wv.z;
        w_s[(t * 32 + co4 + 3) * 36 + ci] = wv.w;
    }
    // inputs: stage ONLY active cells; 8 threads per window cell
    {
        int q = tid & 7;
        for (int p = tid >> 3; p < 561; p += 32) {  // 561 = 17*33
            int r = p / 33;
            int cc = p - r * 33;
            int gy = iy0 + r;
            int gx = ix0 + cc;
            unsigned char mv = 0;
            if ((unsigned)gy < (unsigned)Hin && (unsigned)gx < (unsigned)Hin)
                mv = mi[((size_t)b * Hin + gy) * Hin + gx];
            if (q == 0) m_s[r * 34 + cc] = mv;
            if (mv) {
                const float4* src = (const float4*)(in + (((size_t)b * Hin + gy) * Hin + gx) * 32);
                ((float4*)(in_s + (r * 33 + cc) * 32))[q] = src[q];
            }
        }
    }
    __syncthreads();

    int py = tid >> 5;
    int co = tid & 31;
    float acc[16];
#pragma unroll
    for (int i = 0; i < 16; i++) acc[i] = 0.0f;

#pragma unroll
    for (int t = 0; t < 9; t++) {
        int dy = t / 3;
        int dx = t - dy * 3;
        int row = 2 * py + dy;
        unsigned bm = __ballot_sync(0xFFFFFFFFu,
            (co < 16) && m_s[row * 34 + 2 * (co & 15) + dx]);
        if (!bm) continue;
        float4 wq[8];
        const float4* wv = (const float4*)(w_s + (t * 32 + co) * 36);
#pragma unroll
        for (int qq = 0; qq < 8; qq++) wq[qq] = wv[qq];
        const float* irow = in_s + (row * 33 + dx) * 32;
        while (bm) {
            int px = __ffs(bm) - 1;
            bm &= bm - 1;
            const float4* ip = (const float4*)(irow + px * 64);
#pragma unroll
            for (int qq = 0; qq < 8; qq++) {
                float4 a = ip[qq];
                acc[px] = fmaf(a.x, wq[qq].x, acc[px]);
                acc[px] = fmaf(a.y, wq[qq].y, acc[px]);
                acc[px] = fmaf(a.z, wq[qq].z, acc[px]);
                acc[px] = fmaf(a.w, wq[qq].w, acc[px]);
            }
        }
    }

    // store only active output pixels (downstream reads only active cells)
    int oy = oy0 + py;
    unsigned sm = __ballot_sync(0xFFFFFFFFu,
        (co < 16) && mo[((size_t)b * Hout + oy) * Hout + ox0 + (co & 15)]);
    float* orow = out + (((size_t)b * Hout + oy) * Hout + ox0) * 32 + co;
    while (sm) {
        int px = __ffs(sm) - 1;
        sm &= sm - 1;
        orow[px * 32] = fmaxf(acc[px], 0.0f);
    }
}

// ---------------- masked global pool + MLP head (mask-gated reads) ---------
__global__ void k_final(
    const float* __restrict__ x2,
    const float* __restrict__ W1, const float* __restrict__ b1,
    const float* __restrict__ W2, const float* __restrict__ b2,
    const float* __restrict__ W3, const float* __restrict__ b3,
    float* __restrict__ out)
{
    __shared__ float s_pool[8][32];
    __shared__ int s_cnt[8];
    __shared__ float s_z[64];
    __shared__ float s_t1[64];

    int b = blockIdx.x;
    int tid = threadIdx.x;
    int wg = tid >> 5;
    int lane = tid & 31;

    float ps = 0.0f;
    int pc = 0;
    const float* y4b = g_y4 + (size_t)b * 4096 * 32;
    const unsigned char* m4b = g_m4 + (size_t)b * 4096;
    for (int p = wg; p < 4096; p += 8) {
        if (m4b[p]) {                      // y4 is sparse: gate reads on mask
            ps += y4b[(size_t)p * 32 + lane];
            pc++;
        }
    }
    s_pool[wg][lane] = ps;
    if (lane == 0) s_cnt[wg] = pc;
    __syncthreads();

    if (tid < 32) {
        float s = 0.0f;
        int c = 0;
#pragma unroll
        for (int w = 0; w < 8; w++) { s += s_pool[w][tid]; c += s_cnt[w]; }
        s_z[tid] = s / fmaxf((float)c, 1.0f);
    }
    if (tid < 64) {
        float a = b1[tid];
        a = fmaf(x2[b * 3 + 0], W1[0 * 64 + tid], a);
        a = fmaf(x2[b * 3 + 1], W1[1 * 64 + tid], a);
        a = fmaf(x2[b * 3 + 2], W1[2 * 64 + tid], a);
        s_t1[tid] = fmaxf(a, 0.0f);
    }
    __syncthreads();
    if (tid < 32) {
        float a = b2[tid];
#pragma unroll
        for (int k = 0; k < 64; k++) a = fmaf(s_t1[k], W2[k * 32 + tid], a);
        s_z[32 + tid] = a;
    }
    __syncthreads();
    if (tid < 128) {
        float a = b3[tid];
#pragma unroll
        for (int k = 0; k < 64; k++) a = fmaf(s_z[k], W3[k * 128 + tid], a);
        out[b * 128 + tid] = fmaxf(a, 0.0f);
    }
}

// ---------------- launch ----------------
extern "C" void kernel_launch(void* const* d_in, const int* in_sizes, int n_in,
                              void* d_out, int out_size) {
    const int* coords = (const int*)d_in[0];
    const float* feats = (const float*)d_in[1];
    const float* x2 = (const float*)d_in[2];
    const float* K1 = (const float*)d_in[3];
    const float* K2 = (const float*)d_in[4];
    const float* K3 = (const float*)d_in[5];
    const float* K4 = (const float*)d_in[6];
    const float* W1 = (const float*)d_in[7];
    const float* b1 = (const float*)d_in[8];
    const float* W2 = (const float*)d_in[9];
    const float* b2 = (const float*)d_in[10];
    const float* W3 = (const float*)d_in[11];
    const float* b3 = (const float*)d_in[12];
    float* out = (float*)d_out;

    int npts = in_sizes[0] / 3;  // 262144

    cudaFuncSetAttribute(k_conv_s2<0>, cudaFuncAttributeMaxDynamicSharedMemorySize, CONV_SMEM);
    cudaFuncSetAttribute(k_conv_s2<1>, cudaFuncAttributeMaxDynamicSharedMemorySize, CONV_SMEM);
    cudaFuncSetAttribute(k_conv_s2<2>, cudaFuncAttributeMaxDynamicSharedMemorySize, CONV_SMEM);

    k_reset<<<2048, 256>>>();
    k_scatter<<<(npts + 255) / 256, 256>>>(coords, feats, npts);
    k_decode<<<4096, 256>>>();
    k_maskdown<0><<<(BB * 256 * 256) / 256, 256>>>();
    k_maskdown<1><<<(BB * 128 * 128) / 256, 256>>>();
    k_maskdown<2><<<(BB * 64 * 64) / 256, 256>>>();
    k_conv1<<<dim3(32, 64, BB), 256>>>(K1);
    k_conv_s2<0><<<dim3(16, 32, BB), 256, CONV_SMEM>>>(K2);
    k_conv_s2<1><<<dim3(8, 16, BB), 256, CONV_SMEM>>>(K3);
    k_conv_s2<2><<<dim3(4, 8, BB), 256, CONV_SMEM>>>(K4);
    k_final<<<BB, 256>>>(x2, W1, b1, W2, b2, W3, b3, out);
}

// round 7
// speedup vs baseline: 2.8974x; 1.3481x over previous
#include <cuda_runtime.h>
#include <cstdint>

#define BB 8
#define GSZ 512
#define CC 32

// RULE: g_* symbols are referenced ONLY inside device code (host-shadow bug, R1-R4).
__device__ __align__(16) unsigned long long g_scat[BB * GSZ * GSZ];
__device__ __align__(16) float g_grid[BB * GSZ * GSZ];
__device__ __align__(16) unsigned char g_m1[BB * GSZ * GSZ];
__device__ __align__(16) unsigned char g_m2[BB * 256 * 256];
__device__ __align__(16) unsigned char g_m3[BB * 128 * 128];
__device__ __align__(16) unsigned char g_m4[BB * 64 * 64];
__device__ __align__(16) float g_y1[(size_t)BB * GSZ * GSZ * CC];
__device__ __align__(16) float g_y2[(size_t)BB * 256 * 256 * CC];
__device__ __align__(16) float g_y3[(size_t)BB * 128 * 128 * CC];
__device__ __align__(16) float g_y4[(size_t)BB * 64 * 64 * CC];

// ---------------- reset ----------------
__global__ void k_reset() {
    int n = BB * GSZ * GSZ;
    for (int i = blockIdx.x * blockDim.x + threadIdx.x; i < n; i += gridDim.x * blockDim.x)
        g_scat[i] = 0ULL;
}

// ---------------- scatter: LAST-write-wins via packed (i+1, bits) ----------
__global__ void k_scatter(const int* __restrict__ coords, const float* __restrict__ feats, int n) {
    int i = blockIdx.x * blockDim.x + threadIdx.x;
    if (i >= n) return;
    int b = coords[3 * i + 0];
    int y = coords[3 * i + 1];
    int x = coords[3 * i + 2];
    unsigned long long v = ((unsigned long long)(unsigned)(i + 1) << 32) |
                           (unsigned long long)__float_as_uint(feats[i]);
    atomicMax(&g_scat[((size_t)b * GSZ + y) * GSZ + x], v);
}

// ---------------- decode packed -> grid + m1 ----------------
__global__ void k_decode() {
    int n = BB * GSZ * GSZ;
    for (int i = blockIdx.x * blockDim.x + threadIdx.x; i < n; i += gridDim.x * blockDim.x) {
        unsigned long long v = g_scat[i];
        g_m1[i] = v ? (unsigned char)1 : (unsigned char)0;
        g_grid[i] = v ? __uint_as_float((unsigned)v) : 0.0f;
    }
}

// ---------------- 2x2 max-pool of mask: 4 outputs/thread, uint2 loads ------
template <int L>
__global__ void k_maskdown() {
    const unsigned char* mi = (L == 0) ? g_m1 : (L == 1) ? g_m2 : g_m3;
    unsigned char* mo = (L == 0) ? g_m2 : (L == 1) ? g_m3 : g_m4;
    const int Hout = (L == 0) ? 256 : (L == 1) ? 128 : 64;
    const int Hin = Hout * 2;
    const int W4 = Hout / 4;

    int tot = BB * Hout * W4;
    int i = blockIdx.x * blockDim.x + threadIdx.x;
    if (i >= tot) return;
    int x4 = (i % W4) * 4;
    int y = (i / W4) % Hout;
    int b = i / (W4 * Hout);

    const unsigned char* base = mi + ((size_t)b * Hin + 2 * y) * Hin + 2 * x4;
    uint2 r0 = *(const uint2*)base;
    uint2 r1 = *(const uint2*)(base + Hin);
    unsigned a = r0.x | r1.x;
    unsigned c = r0.y | r1.y;
    unsigned oa = a | (a >> 8);   // byte0=in0|in1, byte2=in2|in3
    unsigned oc = c | (c >> 8);
    unsigned res = (oa & 0xFFu) | ((oa >> 8) & 0xFF00u) |
                   ((oc & 0xFFu) << 16) | (((oc >> 16) & 0xFFu) << 24);
    *(unsigned*)(mo + ((size_t)b * Hout + y) * Hout + x4) = res;
}

// ---------------- SPARSE conv1: 5x5 s1 pad2, 1->32 ch ----------------------
__global__ void k_conv1(const float* __restrict__ K1) {
    __shared__ float in_s[12 * 20];
    __shared__ unsigned char m_s[8 * 16];

    int tid = threadIdx.x;
    int b = blockIdx.z;
    int ox0 = blockIdx.x * 16;
    int oy0 = blockIdx.y * 8;
    int co = tid & 31;
    int py = tid >> 5;

    float w[25];
#pragma unroll
    for (int t = 0; t < 25; t++) w[t] = __ldg(&K1[t * 32 + co]);

    for (int p = tid; p < 240; p += 256) {
        int r = p / 20;
        int c = p - r * 20;
        int gy = oy0 + r - 2;
        int gx = ox0 + c - 2;
        float v = 0.0f;
        if ((unsigned)gy < (unsigned)GSZ && (unsigned)gx < (unsigned)GSZ)
            v = g_grid[((size_t)b * GSZ + gy) * GSZ + gx];
        in_s[p] = v;
    }
    for (int p = tid; p < 128; p += 256) {
        m_s[p] = g_m1[((size_t)b * GSZ + oy0 + (p >> 4)) * GSZ + ox0 + (p & 15)];
    }
    __syncthreads();

    unsigned bm = __ballot_sync(0xFFFFFFFFu, (co < 16) && m_s[py * 16 + co]);
    float* orow = g_y1 + (((size_t)b * GSZ + oy0 + py) * GSZ + ox0) * 32 + co;
    while (bm) {
        int px = __ffs(bm) - 1;
        bm &= bm - 1;
        float acc = 0.0f;
#pragma unroll
        for (int t = 0; t < 25; t++) {
            int dy = t / 5;
            int dx = t - dy * 5;
            acc = fmaf(in_s[(py + dy) * 20 + px + dx], w[t], acc);
        }
        orow[px * 32] = fmaxf(acc, 0.0f);
    }
}

// ---------------- SPARSE 3x3 stride-2 pad-1 conv, 32->32 ch ----------------
// Tile 16(x) x 8(y) outputs; 256 threads; warp = output row, lane = co.
// Two-phase staging: (A) mask scan + warp-aggregated active-cell compaction,
// (B) flat MLP-friendly copy of active cells only.
#define CONV_INS 17952                       // 17*33*32 floats
#define CONV_WS 10368                        // 9*32*36 floats
#define CONV_SMEM ((CONV_INS + CONV_WS) * 4 + 17 * 34 + 2 + 561 * 2)

template <int L>
__global__ __launch_bounds__(256, 2) void k_conv_s2(const float* __restrict__ Kw) {
    const float* in = (L == 0) ? g_y1 : (L == 1) ? g_y2 : g_y3;
    float* out = (L == 0) ? g_y2 : (L == 1) ? g_y3 : g_y4;
    const unsigned char* mi = (L == 0) ? g_m1 : (L == 1) ? g_m2 : g_m3;
    const unsigned char* mo = (L == 0) ? g_m2 : (L == 1) ? g_m3 : g_m4;
    const int Hin = (L == 0) ? 512 : (L == 1) ? 256 : 128;
    const int Hout = Hin / 2;

    extern __shared__ float smem[];
    float* in_s = smem;                                   // [561][32]
    float* w_s = smem + CONV_INS;                         // [9][32][36]
    unsigned char* m_s = (unsigned char*)(smem + CONV_INS + CONV_WS);   // [17*34]
    unsigned short* s_cell = (unsigned short*)(m_s + 17 * 34 + 2);      // [561]
    __shared__ int s_nact;

    int tid = threadIdx.x;
    int lane = tid & 31;
    int b = blockIdx.z;
    int ox0 = blockIdx.x * 16;
    int oy0 = blockIdx.y * 8;
    int ix0 = 2 * ox0 - 1;
    int iy0 = 2 * oy0 - 1;

    const float* in_b = in + (size_t)b * Hin * Hin * 32;
    const unsigned char* mi_b = mi + (size_t)b * Hin * Hin;

    if (tid == 0) s_nact = 0;
    __syncthreads();

    // weights: float4 over co; w_s[tap][co][ci] padded 36
    for (int i4 = tid; i4 < 2304; i4 += 256) {      // 9*32*8
        int t = i4 >> 8;
        int rem = i4 & 255;
        int ci = rem >> 3;
        int co4 = (rem & 7) * 4;
        float4 wv = __ldg((const float4*)Kw + i4);
        w_s[(t * 32 + co4 + 0) * 36 + ci] = wv.x;
        w_s[(t * 32 + co4 + 1) * 36 + ci] = wv.y;
        w_s[(t * 32 + co4 + 2) * 36 + ci] = wv.z;
        w_s[(t * 32 + co4 + 3) * 36 + ci] = wv.w;
    }

    // Phase A: mask scan + compaction (3 full-warp passes over 561 cells)
#pragma unroll
    for (int it = 0; it < 3; it++) {
        int p = tid + it * 256;
        bool valid = p < 561;
        unsigned char mv = 0;
        if (valid) {
            int r = p / 33;
            int c = p - r * 33;
            int gy = iy0 + r;
            int gx = ix0 + c;
            if ((unsigned)gy < (unsigned)Hin && (unsigned)gx < (unsigned)Hin)
                mv = mi_b[gy * Hin + gx];
            m_s[r * 34 + c] = mv;
        }
        unsigned vote = __ballot_sync(0xFFFFFFFFu, valid && mv);
        int base = 0;
        if (lane == 0 && vote) base = atomicAdd(&s_nact, __popc(vote));
        base = __shfl_sync(0xFFFFFFFFu, base, 0);
        if (valid && mv) {
            int pos = base + __popc(vote & ((1u << lane) - 1));
            s_cell[pos] = (unsigned short)p;
        }
    }
    __syncthreads();

    // Phase B: copy active cells, flat loop -> full MLP
    int nact = s_nact;
    for (int i = tid; i < nact * 8; i += 256) {
        int k = i >> 3;
        int q = i & 7;
        int cell = s_cell[k];
        int r = cell / 33;
        int c = cell - r * 33;
        int gy = iy0 + r;
        int gx = ix0 + c;
        float4 v = __ldg((const float4*)(in_b + (size_t)(gy * Hin + gx) * 32) + q);
        ((float4*)(in_s + cell * 32))[q] = v;
    }
    __syncthreads();

    int py = tid >> 5;
    int co = tid & 31;
    float acc[16];
#pragma unroll
    for (int i = 0; i < 16; i++) acc[i] = 0.0f;

    int oy = oy0 + py;
    // output-active px mask for this row (bits 0..15)
    unsigned sm = __ballot_sync(0xFFFFFFFFu,
        (co < 16) && mo[((size_t)b * Hout + oy) * Hout + ox0 + (co & 15)]);

    if (sm) {
#pragma unroll
        for (int t = 0; t < 9; t++) {
            int dy = t / 3;
            int dx = t - dy * 3;
            int row = 2 * py + dy;
            unsigned bm = __ballot_sync(0xFFFFFFFFu,
                (co < 16) && m_s[row * 34 + 2 * (co & 15) + dx]);
            bm &= sm;                        // only px with active outputs
            if (!bm) continue;
            float4 wq[8];
            const float4* wv = (const float4*)(w_s + (t * 32 + co) * 36);
#pragma unroll
            for (int qq = 0; qq < 8; qq++) wq[qq] = wv[qq];
            const float* irow = in_s + (row * 33 + dx) * 32;
            while (bm) {
                int px = __ffs(bm) - 1;
                bm &= bm - 1;
                const float4* ip = (const float4*)(irow + px * 64);
#pragma unroll
                for (int qq = 0; qq < 8; qq++) {
                    float4 a = ip[qq];
                    acc[px] = fmaf(a.x, wq[qq].x, acc[px]);
                    acc[px] = fmaf(a.y, wq[qq].y, acc[px]);
                    acc[px] = fmaf(a.z, wq[qq].z, acc[px]);
                    acc[px] = fmaf(a.w, wq[qq].w, acc[px]);
                }
            }
        }
        float* orow = out + (((size_t)b * Hout + oy) * Hout + ox0) * 32 + co;
        unsigned st = sm;
        while (st) {
            int px = __ffs(st) - 1;
            st &= st - 1;
            orow[px * 32] = fmaxf(acc[px], 0.0f);
        }
    }
}

// ---------------- masked global pool + MLP head (1024 threads) -------------
__global__ void k_final(
    const float* __restrict__ x2,
    const float* __restrict__ W1, const float* __restrict__ b1,
    const float* __restrict__ W2, const float* __restrict__ b2,
    const float* __restrict__ W3, const float* __restrict__ b3,
    float* __restrict__ out)
{
    __shared__ float s_pool[32][32];
    __shared__ int s_cnt[32];
    __shared__ float s_z[64];
    __shared__ float s_t1[64];

    int b = blockIdx.x;
    int tid = threadIdx.x;
    int wg = tid >> 5;
    int lane = tid & 31;

    float ps = 0.0f;
    int pc = 0;
    const float* y4b = g_y4 + (size_t)b * 4096 * 32;
    const unsigned char* m4b = g_m4 + (size_t)b * 4096;
    for (int p = wg; p < 4096; p += 32) {
        if (m4b[p]) {
            ps += y4b[(size_t)p * 32 + lane];
            pc++;
        }
    }
    s_pool[wg][lane] = ps;
    if (lane == 0) s_cnt[wg] = pc;
    __syncthreads();

    if (tid < 32) {
        float s = 0.0f;
        int c = 0;
#pragma unroll
        for (int w = 0; w < 32; w++) { s += s_pool[w][tid]; c += s_cnt[w]; }
        s_z[tid] = s / fmaxf((float)c, 1.0f);
    }
    if (tid >= 32 && tid < 96) {
        int t = tid - 32;
        float a = b1[t];
        a = fmaf(x2[b * 3 + 0], W1[0 * 64 + t], a);
        a = fmaf(x2[b * 3 + 1], W1[1 * 64 + t], a);
        a = fmaf(x2[b * 3 + 2], W1[2 * 64 + t], a);
        s_t1[t] = fmaxf(a, 0.0f);
    }
    __syncthreads();
    if (tid < 32) {
        float a = b2[tid];
#pragma unroll
        for (int k = 0; k < 64; k++) a = fmaf(s_t1[k], W2[k * 32 + tid], a);
        s_z[32 + tid] = a;
    }
    __syncthreads();
    if (tid < 128) {
        float a = b3[tid];
#pragma unroll
        for (int k = 0; k < 64; k++) a = fmaf(s_z[k], W3[k * 128 + tid], a);
        out[b * 128 + tid] = fmaxf(a, 0.0f);
    }
}

// ---------------- launch ----------------
extern "C" void kernel_launch(void* const* d_in, const int* in_sizes, int n_in,
                              void* d_out, int out_size) {
    const int* coords = (const int*)d_in[0];
    const float* feats = (const float*)d_in[1];
    const float* x2 = (const float*)d_in[2];
    const float* K1 = (const float*)d_in[3];
    const float* K2 = (const float*)d_in[4];
    const float* K3 = (const float*)d_in[5];
    const float* K4 = (const float*)d_in[6];
    const float* W1 = (const float*)d_in[7];
    const float* b1 = (const float*)d_in[8];
    const float* W2 = (const float*)d_in[9];
    const float* b2 = (const float*)d_in[10];
    const float* W3 = (const float*)d_in[11];
    const float* b3 = (const float*)d_in[12];
    float* out = (float*)d_out;

    int npts = in_sizes[0] / 3;  // 262144

    cudaFuncSetAttribute(k_conv_s2<0>, cudaFuncAttributeMaxDynamicSharedMemorySize, CONV_SMEM);
    cudaFuncSetAttribute(k_conv_s2<1>, cudaFuncAttributeMaxDynamicSharedMemorySize, CONV_SMEM);
    cudaFuncSetAttribute(k_conv_s2<2>, cudaFuncAttributeMaxDynamicSharedMemorySize, CONV_SMEM);

    // Order chosen so the ncu capture window (-s 5 -c 1) lands on a conv kernel.
    k_reset<<<2048, 256>>>();
    k_scatter<<<(npts + 255) / 256, 256>>>(coords, feats, npts);
    k_decode<<<4096, 256>>>();
    k_conv1<<<dim3(32, 64, BB), 256>>>(K1);
    k_maskdown<0><<<(BB * 256 * 64 + 255) / 256, 256>>>();
    k_conv_s2<0><<<dim3(16, 32, BB), 256, CONV_SMEM>>>(K2);
    k_maskdown<1><<<(BB * 128 * 32 + 255) / 256, 256>>>();
    k_conv_s2<1><<<dim3(8, 16, BB), 256, CONV_SMEM>>>(K3);
    k_maskdown<2><<<(BB * 64 * 16 + 255) / 256, 256>>>();
    k_conv_s2<2><<<dim3(4, 8, BB), 256, CONV_SMEM>>>(K4);
    k_final<<<BB, 1024>>>(x2, W1, b1, W2, b2, W3, b3, out);
}

// round 8
// speedup vs baseline: 3.4040x; 1.1748x over previous
#include <cuda_runtime.h>
#include <cstdint>

#define BB 8
#define GSZ 512
#define CC 32

// RULE: g_* symbols are referenced ONLY inside device code (host-shadow bug, R1-R4).
__device__ __align__(16) unsigned g_key[BB * GSZ * GSZ];            // 8 MB
__device__ __align__(16) float g_grid[BB * GSZ * GSZ];
__device__ __align__(16) unsigned char g_m1[BB * GSZ * GSZ];
__device__ __align__(16) unsigned char g_m2[BB * 256 * 256];
__device__ __align__(16) unsigned char g_m3[BB * 128 * 128];
__device__ __align__(16) unsigned char g_m4[BB * 64 * 64];
__device__ __align__(16) float g_y1[(size_t)BB * GSZ * GSZ * CC];
__device__ __align__(16) float g_y2[(size_t)BB * 256 * 256 * CC];
__device__ __align__(16) float g_y3[(size_t)BB * 128 * 128 * CC];
__device__ __align__(16) float g_y4[(size_t)BB * 64 * 64 * CC];
__device__ __align__(16) float g_wt[3 * 9 * 32 * 36];               // pre-transposed weights

// ---------------- reset (32-bit keys, uint4 stores) ----------------
__global__ void k_reset() {
    int n = (BB * GSZ * GSZ) / 4;
    uint4 z = make_uint4(0, 0, 0, 0);
    for (int i = blockIdx.x * blockDim.x + threadIdx.x; i < n; i += gridDim.x * blockDim.x)
        ((uint4*)g_key)[i] = z;
}

// ---------------- scatter: LAST-write-wins, key-only 32-bit atomics --------
__global__ void k_scatter(const int* __restrict__ coords, int n) {
    int i = blockIdx.x * blockDim.x + threadIdx.x;
    if (i >= n) return;
    int b = __ldg(&coords[3 * i + 0]);
    int y = __ldg(&coords[3 * i + 1]);
    int x = __ldg(&coords[3 * i + 2]);
    atomicMax(&g_key[((size_t)b * GSZ + y) * GSZ + x], (unsigned)(i + 1));
}

// ---------------- decode: key -> mask + gathered feat ----------------
__global__ void k_decode(const float* __restrict__ feats) {
    int n = BB * GSZ * GSZ;
    for (int i = blockIdx.x * blockDim.x + threadIdx.x; i < n; i += gridDim.x * blockDim.x) {
        unsigned v = g_key[i];
        g_m1[i] = v ? (unsigned char)1 : (unsigned char)0;
        g_grid[i] = v ? __ldg(&feats[v - 1]) : 0.0f;
    }
}

// ---------------- one-time weight transpose: HWIO -> [tap][co][ci pad 36] --
__global__ void k_wtrans(const float* __restrict__ K2, const float* __restrict__ K3,
                         const float* __restrict__ K4) {
    int L = blockIdx.x;
    const float* src = (L == 0) ? K2 : (L == 1) ? K3 : K4;
    float* dst = g_wt + L * 10368;
    for (int i = threadIdx.x; i < 9216; i += blockDim.x) {
        int t = i >> 10;
        int rem = i & 1023;
        int ci = rem >> 5;
        int co = rem & 31;
        dst[(t * 32 + co) * 36 + ci] = __ldg(&src[i]);
    }
}

// ---------------- fused mask downsample: m1 -> m2,m3,m4 --------------------
// One thread per m4 cell: reads 8x8 m1 block, writes 4x4 m2, 2x2 m3, 1 m4.
__global__ void k_maskall() {
    int i = blockIdx.x * blockDim.x + threadIdx.x;
    if (i >= BB * 64 * 64) return;
    int X = i & 63;
    int Y = (i >> 6) & 63;
    int b = i >> 12;

    const unsigned char* m1b = g_m1 + ((size_t)b * GSZ + 8 * Y) * GSZ + 8 * X;
    unsigned m2row[4];
    unsigned allor = 0;
#pragma unroll
    for (int r2 = 0; r2 < 4; r2++) {                 // m2 row within block
        uint2 a = *(const uint2*)(m1b + (2 * r2) * GSZ);
        uint2 c = *(const uint2*)(m1b + (2 * r2 + 1) * GSZ);
        unsigned u = a.x | c.x;                      // m1 cols 0..3
        unsigned v = a.y | c.y;                      // m1 cols 4..7
        unsigned tu = u | (u >> 8);
        unsigned tv = v | (v >> 8);
        unsigned res = (tu & 0xFFu) | (((tu >> 16) & 0xFFu) << 8) |
                       ((tv & 0xFFu) << 16) | (((tv >> 16) & 0xFFu) << 24);
        m2row[r2] = res;
        allor |= res;
        *(unsigned*)(g_m2 + ((size_t)b * 256 + 4 * Y + r2) * 256 + 4 * X) = res;
    }
#pragma unroll
    for (int r3 = 0; r3 < 2; r3++) {                 // m3 row within block
        unsigned w = m2row[2 * r3] | m2row[2 * r3 + 1];
        unsigned s = w | (w >> 8);
        unsigned short m3v = (unsigned short)((s & 0xFFu) | (((s >> 16) & 0xFFu) << 8));
        *(unsigned short*)(g_m3 + ((size_t)b * 128 + 2 * Y + r3) * 128 + 2 * X) = m3v;
    }
    unsigned o = allor;
    o |= o >> 16;
    o |= o >> 8;
    g_m4[((size_t)b * 64 + Y) * 64 + X] = (unsigned char)(o & 1u);
}

// ---------------- SPARSE conv1: 5x5 s1 pad2, 1->32 ch (unchanged control) --
__global__ void k_conv1(const float* __restrict__ K1) {
    __shared__ float in_s[12 * 20];
    __shared__ unsigned char m_s[8 * 16];

    int tid = threadIdx.x;
    int b = blockIdx.z;
    int ox0 = blockIdx.x * 16;
    int oy0 = blockIdx.y * 8;
    int co = tid & 31;
    int py = tid >> 5;

    float w[25];
#pragma unroll
    for (int t = 0; t < 25; t++) w[t] = __ldg(&K1[t * 32 + co]);

    for (int p = tid; p < 240; p += 256) {
        int r = p / 20;
        int c = p - r * 20;
        int gy = oy0 + r - 2;
        int gx = ox0 + c - 2;
        float v = 0.0f;
        if ((unsigned)gy < (unsigned)GSZ && (unsigned)gx < (unsigned)GSZ)
            v = g_grid[((size_t)b * GSZ + gy) * GSZ + gx];
        in_s[p] = v;
    }
    for (int p = tid; p < 128; p += 256) {
        m_s[p] = g_m1[((size_t)b * GSZ + oy0 + (p >> 4)) * GSZ + ox0 + (p & 15)];
    }
    __syncthreads();

    unsigned bm = __ballot_sync(0xFFFFFFFFu, (co < 16) && m_s[py * 16 + co]);
    float* orow = g_y1 + (((size_t)b * GSZ + oy0 + py) * GSZ + ox0) * 32 + co;
    while (bm) {
        int px = __ffs(bm) - 1;
        bm &= bm - 1;
        float acc = 0.0f;
#pragma unroll
        for (int t = 0; t < 25; t++) {
            int dy = t / 5;
            int dx = t - dy * 5;
            acc = fmaf(in_s[(py + dy) * 20 + px + dx], w[t], acc);
        }
        orow[px * 32] = fmaxf(acc, 0.0f);
    }
}

// ---------------- SPARSE 3x3 stride-2 pad-1 conv, 32->32 ch ----------------
// Tile 16(x) x 8(y); warp = output row, lane = co. Static acc indexing
// (unrolled px loops, warp-uniform guards) - NO local-memory spill.
#define CONV_INS 17952                       // 17*33*32 floats
#define CONV_WS 10368                        // 9*32*36 floats
#define CONV_SMEM ((CONV_INS + CONV_WS) * 4 + 17 * 34 + 2 + 561 * 2)

template <int L>
__global__ __launch_bounds__(256, 2) void k_conv_s2() {
    const float* in = (L == 0) ? g_y1 : (L == 1) ? g_y2 : g_y3;
    float* out = (L == 0) ? g_y2 : (L == 1) ? g_y3 : g_y4;
    const unsigned char* mi = (L == 0) ? g_m1 : (L == 1) ? g_m2 : g_m3;
    const unsigned char* mo = (L == 0) ? g_m2 : (L == 1) ? g_m3 : g_m4;
    const int Hin = (L == 0) ? 512 : (L == 1) ? 256 : 128;
    const int Hout = Hin / 2;

    extern __shared__ float smem[];
    float* in_s = smem;                                   // [561][32]
    float* w_s = smem + CONV_INS;                         // [9][32][36]
    unsigned char* m_s = (unsigned char*)(smem + CONV_INS + CONV_WS);
    unsigned short* s_cell = (unsigned short*)(m_s + 17 * 34 + 2);
    __shared__ int s_nact;

    int tid = threadIdx.x;
    int lane = tid & 31;
    int b = blockIdx.z;
    int ox0 = blockIdx.x * 16;
    int oy0 = blockIdx.y * 8;
    int ix0 = 2 * ox0 - 1;
    int iy0 = 2 * oy0 - 1;

    const float* in_b = in + (size_t)b * Hin * Hin * 32;
    const unsigned char* mi_b = mi + (size_t)b * Hin * Hin;

    if (tid == 0) s_nact = 0;
    __syncthreads();

    // weights: straight coalesced copy of pre-transposed [tap][co][ci36]
    {
        const float4* wsrc = (const float4*)(g_wt + L * 10368);
        float4* wdst = (float4*)w_s;
        for (int i4 = tid; i4 < 2592; i4 += 256) wdst[i4] = __ldg(wsrc + i4);
    }

    // Phase A: mask scan + warp-aggregated active-cell compaction
#pragma unroll
    for (int it = 0; it < 3; it++) {
        int p = tid + it * 256;
        bool valid = p < 561;
        unsigned char mv = 0;
        if (valid) {
            int r = p / 33;
            int c = p - r * 33;
            int gy = iy0 + r;
            int gx = ix0 + c;
            if ((unsigned)gy < (unsigned)Hin && (unsigned)gx < (unsigned)Hin)
                mv = mi_b[gy * Hin + gx];
            m_s[r * 34 + c] = mv;
        }
        unsigned vote = __ballot_sync(0xFFFFFFFFu, valid && mv);
        int base = 0;
        if (lane == 0 && vote) base = atomicAdd(&s_nact, __popc(vote));
        base = __shfl_sync(0xFFFFFFFFu, base, 0);
        if (valid && mv) {
            int pos = base + __popc(vote & ((1u << lane) - 1));
            s_cell[pos] = (unsigned short)p;
        }
    }
    __syncthreads();

    // Phase B: flat copy of active cells only
    int nact = s_nact;
    for (int i = tid; i < nact * 8; i += 256) {
        int k = i >> 3;
        int q = i & 7;
        int cell = s_cell[k];
        int r = cell / 33;
        int c = cell - r * 33;
        int gy = iy0 + r;
        int gx = ix0 + c;
        float4 v = __ldg((const float4*)(in_b + (size_t)(gy * Hin + gx) * 32) + q);
        ((float4*)(in_s + cell * 32))[q] = v;
    }
    __syncthreads();

    int py = tid >> 5;
    int co = tid & 31;
    int oy = oy0 + py;
    unsigned sm = __ballot_sync(0xFFFFFFFFu,
        (co < 16) && mo[((size_t)b * Hout + oy) * Hout + ox0 + (co & 15)]);

    if (sm) {
        float acc[16];
#pragma unroll
        for (int i = 0; i < 16; i++) acc[i] = 0.0f;

#pragma unroll 1
        for (int t = 0; t < 9; t++) {
            int dy = t / 3;
            int dx = t - dy * 3;
            int row = 2 * py + dy;
            unsigned bm = __ballot_sync(0xFFFFFFFFu,
                (co < 16) && m_s[row * 34 + 2 * (co & 15) + dx]);
            bm &= sm;
            if (!bm) continue;
            float4 wq[8];
            const float4* wv = (const float4*)(w_s + (t * 32 + co) * 36);
#pragma unroll
            for (int qq = 0; qq < 8; qq++) wq[qq] = wv[qq];
            const float* irow = in_s + (row * 33 + dx) * 32;
#pragma unroll
            for (int px = 0; px < 16; px++) {
                if (bm & (1u << px)) {                // warp-uniform branch
                    const float4* ip = (const float4*)(irow + px * 64);
#pragma unroll
                    for (int qq = 0; qq < 8; qq++) {
                        float4 a = ip[qq];
                        acc[px] = fmaf(a.x, wq[qq].x, acc[px]);
                        acc[px] = fmaf(a.y, wq[qq].y, acc[px]);
                        acc[px] = fmaf(a.z, wq[qq].z, acc[px]);
                        acc[px] = fmaf(a.w, wq[qq].w, acc[px]);
                    }
                }
            }
        }
        float* orow = out + (((size_t)b * Hout + oy) * Hout + ox0) * 32 + co;
#pragma unroll
        for (int px = 0; px < 16; px++) {
            if (sm & (1u << px)) orow[px * 32] = fmaxf(acc[px], 0.0f);
        }
    }
}

// ---------------- masked global pool + MLP head (1024 threads) -------------
__global__ void k_final(
    const float* __restrict__ x2,
    const float* __restrict__ W1, const float* __restrict__ b1,
    const float* __restrict__ W2, const float* __restrict__ b2,
    const float* __restrict__ W3, const float* __restrict__ b3,
    float* __restrict__ out)
{
    __shared__ float s_pool[32][32];
    __shared__ int s_cnt[32];
    __shared__ float s_z[64];
    __shared__ float s_t1[64];

    int b = blockIdx.x;
    int tid = threadIdx.x;
    int wg = tid >> 5;
    int lane = tid & 31;

    float ps = 0.0f;
    int pc = 0;
    const float* y4b = g_y4 + (size_t)b * 4096 * 32;
    const unsigned char* m4b = g_m4 + (size_t)b * 4096;
    for (int p = wg; p < 4096; p += 32) {
        if (m4b[p]) {
            ps += y4b[(size_t)p * 32 + lane];
            pc++;
        }
    }
    s_pool[wg][lane] = ps;
    if (lane == 0) s_cnt[wg] = pc;
    __syncthreads();

    if (tid < 32) {
        float s = 0.0f;
        int c = 0;
#pragma unroll
        for (int w = 0; w < 32; w++) { s += s_pool[w][tid]; c += s_cnt[w]; }
        s_z[tid] = s / fmaxf((float)c, 1.0f);
    }
    if (tid >= 32 && tid < 96) {
        int t = tid - 32;
        float a = b1[t];
        a = fmaf(x2[b * 3 + 0], W1[0 * 64 + t], a);
        a = fmaf(x2[b * 3 + 1], W1[1 * 64 + t], a);
        a = fmaf(x2[b * 3 + 2], W1[2 * 64 + t], a);
        s_t1[t] = fmaxf(a, 0.0f);
    }
    __syncthreads();
    if (tid < 32) {
        float a = b2[tid];
#pragma unroll
        for (int k = 0; k < 64; k++) a = fmaf(s_t1[k], W2[k * 32 + tid], a);
        s_z[32 + tid] = a;
    }
    __syncthreads();
    if (tid < 128) {
        float a = b3[tid];
#pragma unroll
        for (int k = 0; k < 64; k++) a = fmaf(s_z[k], W3[k * 128 + tid], a);
        out[b * 128 + tid] = fmaxf(a, 0.0f);
    }
}

// ---------------- launch ----------------
extern "C" void kernel_launch(void* const* d_in, const int* in_sizes, int n_in,
                              void* d_out, int out_size) {
    const int* coords = (const int*)d_in[0];
    const float* feats = (const float*)d_in[1];
    const float* x2 = (const float*)d_in[2];
    const float* K1 = (const float*)d_in[3];
    const float* K2 = (const float*)d_in[4];
    const float* K3 = (const float*)d_in[5];
    const float* K4 = (const float*)d_in[6];
    const float* W1 = (const float*)d_in[7];
    const float* b1 = (const float*)d_in[8];
    const float* W2 = (const float*)d_in[9];
    const float* b2 = (const float*)d_in[10];
    const float* W3 = (const float*)d_in[11];
    const float* b3 = (const float*)d_in[12];
    float* out = (float*)d_out;

    int npts = in_sizes[0] / 3;  // 262144

    cudaFuncSetAttribute(k_conv_s2<0>, cudaFuncAttributeMaxDynamicSharedMemorySize, CONV_SMEM);
    cudaFuncSetAttribute(k_conv_s2<1>, cudaFuncAttributeMaxDynamicSharedMemorySize, CONV_SMEM);
    cudaFuncSetAttribute(k_conv_s2<2>, cudaFuncAttributeMaxDynamicSharedMemorySize, CONV_SMEM);

    k_reset<<<2048, 256>>>();
    k_scatter<<<(npts + 255) / 256, 256>>>(coords, npts);
    k_decode<<<4096, 256>>>(feats);
    k_conv1<<<dim3(32, 64, BB), 256>>>(K1);          // launch #4 = profiled (control)
    k_wtrans<<<3, 256>>>(K2, K3, K4);
    k_maskall<<<(BB * 64 * 64) / 256, 256>>>();
    k_conv_s2<0><<<dim3(16, 32, BB), 256, CONV_SMEM>>>();
    k_conv_s2<1><<<dim3(8, 16, BB), 256, CONV_SMEM>>>();
    k_conv_s2<2><<<dim3(4, 8, BB), 256, CONV_SMEM>>>();
    k_final<<<BB, 1024>>>(x2, W1, b1, W2, b2, W3, b3, out);
}

// round 9
// speedup vs baseline: 3.6245x; 1.0648x over previous
#include <cuda_runtime.h>
#include <cstdint>

#define BB 8
#define GSZ 512
#define CC 32

// RULE: g_* symbols are referenced ONLY inside device code (host-shadow bug, R1-R4).
__device__ __align__(16) unsigned g_key[BB * GSZ * GSZ];            // 8 MB
__device__ __align__(16) float g_grid[BB * GSZ * GSZ];
__device__ __align__(16) unsigned char g_m1[BB * GSZ * GSZ];
__device__ __align__(16) unsigned char g_m2[BB * 256 * 256];
__device__ __align__(16) unsigned char g_m3[BB * 128 * 128];
__device__ __align__(16) unsigned char g_m4[BB * 64 * 64];
__device__ __align__(16) float g_y1[(size_t)BB * GSZ * GSZ * CC];
__device__ __align__(16) float g_y2[(size_t)BB * 256 * 256 * CC];
__device__ __align__(16) float g_y3[(size_t)BB * 128 * 128 * CC];
__device__ __align__(16) float g_y4[(size_t)BB * 64 * 64 * CC];
__device__ __align__(16) float g_wt[3 * 9 * 32 * 36];               // pre-transposed weights

// ---------------- scatter: LAST-write-wins, key-only 32-bit atomics --------
// g_key starts zero (BSS) and is re-zeroed by k_decode each invocation.
__global__ void k_scatter(const int* __restrict__ coords, int n) {
    int i = blockIdx.x * blockDim.x + threadIdx.x;
    if (i >= n) return;
    int b = __ldg(&coords[3 * i + 0]);
    int y = __ldg(&coords[3 * i + 1]);
    int x = __ldg(&coords[3 * i + 2]);
    atomicMax(&g_key[((size_t)b * GSZ + y) * GSZ + x], (unsigned)(i + 1));
}

// ---------------- decode: key -> mask + gathered feat; self-clearing -------
__global__ void k_decode(const float* __restrict__ feats) {
    int n = BB * GSZ * GSZ;
    for (int i = blockIdx.x * blockDim.x + threadIdx.x; i < n; i += gridDim.x * blockDim.x) {
        unsigned v = g_key[i];
        g_m1[i] = v ? (unsigned char)1 : (unsigned char)0;
        g_grid[i] = v ? __ldg(&feats[v - 1]) : 0.0f;
        if (v) g_key[i] = 0;                     // conditional clear (sparse writes)
    }
}

// ---------------- conv1 (16x32 tiles) + fused aux (maskall / wtrans) -------
// blockIdx.z < BB : sparse 5x5 conv, tile 16(x) x 32(y), warp w does rows
//                   w, w+8, w+16, w+24; lane = out channel; ballot px skip.
// blockIdx.z == BB: aux slice - 128 blocks do mask pyramid, 3 do wtrans.
__global__ void k_conv1(const float* __restrict__ K1, const float* __restrict__ K2,
                        const float* __restrict__ K3, const float* __restrict__ K4) {
    if (blockIdx.z == BB) {
        int bid = blockIdx.y * 32 + blockIdx.x;
        if (bid < 128) {
            // mask pyramid: one thread per m4 cell (8x8 m1 block)
            int i = bid * 256 + threadIdx.x;
            int X = i & 63;
            int Y = (i >> 6) & 63;
            int b = i >> 12;
            const unsigned char* m1b = g_m1 + ((size_t)b * GSZ + 8 * Y) * GSZ + 8 * X;
            unsigned m2row[4];
            unsigned allor = 0;
#pragma unroll
            for (int r2 = 0; r2 < 4; r2++) {
                uint2 a = *(const uint2*)(m1b + (2 * r2) * GSZ);
                uint2 c = *(const uint2*)(m1b + (2 * r2 + 1) * GSZ);
                unsigned u = a.x | c.x;
                unsigned v = a.y | c.y;
                unsigned tu = u | (u >> 8);
                unsigned tv = v | (v >> 8);
                unsigned res = (tu & 0xFFu) | (((tu >> 16) & 0xFFu) << 8) |
                               ((tv & 0xFFu) << 16) | (((tv >> 16) & 0xFFu) << 24);
                m2row[r2] = res;
                allor |= res;
                *(unsigned*)(g_m2 + ((size_t)b * 256 + 4 * Y + r2) * 256 + 4 * X) = res;
            }
#pragma unroll
            for (int r3 = 0; r3 < 2; r3++) {
                unsigned w = m2row[2 * r3] | m2row[2 * r3 + 1];
                unsigned s = w | (w >> 8);
                unsigned short m3v = (unsigned short)((s & 0xFFu) | (((s >> 16) & 0xFFu) << 8));
                *(unsigned short*)(g_m3 + ((size_t)b * 128 + 2 * Y + r3) * 128 + 2 * X) = m3v;
            }
            unsigned o = allor;
            o |= o >> 16;
            o |= o >> 8;
            g_m4[((size_t)b * 64 + Y) * 64 + X] = (unsigned char)(o & 1u);
        } else if (bid < 131) {
            int L = bid - 128;
            const float* src = (L == 0) ? K2 : (L == 1) ? K3 : K4;
            float* dst = g_wt + L * 10368;
            for (int i = threadIdx.x; i < 9216; i += 256) {
                int t = i >> 10;
                int rem = i & 1023;
                int ci = rem >> 5;
                int co = rem & 31;
                dst[(t * 32 + co) * 36 + ci] = __ldg(&src[i]);
            }
        }
        return;
    }

    __shared__ float in_s[36 * 20];            // (32+4) rows x (16+4) cols
    __shared__ unsigned omask[32];             // 16-bit active-px mask per row

    int tid = threadIdx.x;
    int b = blockIdx.z;
    int ox0 = blockIdx.x * 16;
    int oy0 = blockIdx.y * 32;
    int co = tid & 31;
    int wid = tid >> 5;

    float w[25];
#pragma unroll
    for (int t = 0; t < 25; t++) w[t] = __ldg(&K1[t * 32 + co]);

    // stage input window: 720 floats, 3 per thread (MLP 3)
    for (int p = tid; p < 720; p += 256) {
        int r = p / 20;
        int c = p - r * 20;
        int gy = oy0 + r - 2;
        int gx = ox0 + c - 2;
        float v = 0.0f;
        if ((unsigned)gy < (unsigned)GSZ && (unsigned)gx < (unsigned)GSZ)
            v = g_grid[((size_t)b * GSZ + gy) * GSZ + gx];
        in_s[p] = v;
    }
    // stage output masks: one uint4 per row -> 16-bit bitmask
    if (tid < 32) {
        uint4 m = __ldg((const uint4*)(g_m1 + ((size_t)b * GSZ + oy0 + tid) * GSZ + ox0));
        unsigned wv[4] = {m.x, m.y, m.z, m.w};
        unsigned bits = 0;
#pragma unroll
        for (int j = 0; j < 4; j++)
#pragma unroll
            for (int k = 0; k < 4; k++)
                if ((wv[j] >> (8 * k)) & 0xFFu) bits |= 1u << (j * 4 + k);
        omask[tid] = bits;
    }
    __syncthreads();

#pragma unroll
    for (int rr = 0; rr < 4; rr++) {
        int py = wid + rr * 8;
        unsigned bm = omask[py];               // uniform broadcast
        float* orow = g_y1 + (((size_t)b * GSZ + oy0 + py) * GSZ + ox0) * 32 + co;
        while (bm) {
            int px = __ffs(bm) - 1;
            bm &= bm - 1;
            float acc = 0.0f;
#pragma unroll
            for (int t = 0; t < 25; t++) {
                int dy = t / 5;
                int dx = t - dy * 5;
                acc = fmaf(in_s[(py + dy) * 20 + px + dx], w[t], acc);
            }
            orow[px * 32] = fmaxf(acc, 0.0f);
        }
    }
}

// ---------------- SPARSE 3x3 stride-2 pad-1 conv, 32->32 ch ----------------
#define CONV_INS 17952                       // 17*33*32 floats
#define CONV_WS 10368                        // 9*32*36 floats
#define CONV_SMEM ((CONV_INS + CONV_WS) * 4 + 17 * 34 + 2 + 561 * 2)

template <int L>
__global__ __launch_bounds__(256, 2) void k_conv_s2() {
    const float* in = (L == 0) ? g_y1 : (L == 1) ? g_y2 : g_y3;
    float* out = (L == 0) ? g_y2 : (L == 1) ? g_y3 : g_y4;
    const unsigned char* mi = (L == 0) ? g_m1 : (L == 1) ? g_m2 : g_m3;
    const unsigned char* mo = (L == 0) ? g_m2 : (L == 1) ? g_m3 : g_m4;
    const int Hin = (L == 0) ? 512 : (L == 1) ? 256 : 128;
    const int Hout = Hin / 2;

    extern __shared__ float smem[];
    float* in_s = smem;                                   // [561][32]
    float* w_s = smem + CONV_INS;                         // [9][32][36]
    unsigned char* m_s = (unsigned char*)(smem + CONV_INS + CONV_WS);
    unsigned short* s_cell = (unsigned short*)(m_s + 17 * 34 + 2);
    __shared__ int s_nact;

    int tid = threadIdx.x;
    int lane = tid & 31;
    int b = blockIdx.z;
    int ox0 = blockIdx.x * 16;
    int oy0 = blockIdx.y * 8;
    int ix0 = 2 * ox0 - 1;
    int iy0 = 2 * oy0 - 1;

    const float* in_b = in + (size_t)b * Hin * Hin * 32;
    const unsigned char* mi_b = mi + (size_t)b * Hin * Hin;

    if (tid == 0) s_nact = 0;
    __syncthreads();

    // weights: straight coalesced copy of pre-transposed [tap][co][ci36]
    {
        const float4* wsrc = (const float4*)(g_wt + L * 10368);
        float4* wdst = (float4*)w_s;
        for (int i4 = tid; i4 < 2592; i4 += 256) wdst[i4] = __ldg(wsrc + i4);
    }

    // Phase A: mask scan + warp-aggregated active-cell compaction
#pragma unroll
    for (int it = 0; it < 3; it++) {
        int p = tid + it * 256;
        bool valid = p < 561;
        unsigned char mv = 0;
        if (valid) {
            int r = p / 33;
            int c = p - r * 33;
            int gy = iy0 + r;
            int gx = ix0 + c;
            if ((unsigned)gy < (unsigned)Hin && (unsigned)gx < (unsigned)Hin)
                mv = mi_b[gy * Hin + gx];
            m_s[r * 34 + c] = mv;
        }
        unsigned vote = __ballot_sync(0xFFFFFFFFu, valid && mv);
        int base = 0;
        if (lane == 0 && vote) base = atomicAdd(&s_nact, __popc(vote));
        base = __shfl_sync(0xFFFFFFFFu, base, 0);
        if (valid && mv) {
            int pos = base + __popc(vote & ((1u << lane) - 1));
            s_cell[pos] = (unsigned short)p;
        }
    }
    __syncthreads();

    // Phase B: flat copy of active cells only
    int nact = s_nact;
    for (int i = tid; i < nact * 8; i += 256) {
        int k = i >> 3;
        int q = i & 7;
        int cell = s_cell[k];
        int r = cell / 33;
        int c = cell - r * 33;
        int gy = iy0 + r;
        int gx = ix0 + c;
        float4 v = __ldg((const float4*)(in_b + (size_t)(gy * Hin + gx) * 32) + q);
        ((float4*)(in_s + cell * 32))[q] = v;
    }
    __syncthreads();

    int py = tid >> 5;
    int co = tid & 31;
    int oy = oy0 + py;
    unsigned sm = __ballot_sync(0xFFFFFFFFu,
        (co < 16) && mo[((size_t)b * Hout + oy) * Hout + ox0 + (co & 15)]);

    if (sm) {
        float acc[16];
#pragma unroll
        for (int i = 0; i < 16; i++) acc[i] = 0.0f;

#pragma unroll 1
        for (int t = 0; t < 9; t++) {
            int dy = t / 3;
            int dx = t - dy * 3;
            int row = 2 * py + dy;
            unsigned bm = __ballot_sync(0xFFFFFFFFu,
                (co < 16) && m_s[row * 34 + 2 * (co & 15) + dx]);
            bm &= sm;
            if (!bm) continue;
            float4 wq[8];
            const float4* wv = (const float4*)(w_s + (t * 32 + co) * 36);
#pragma unroll
            for (int qq = 0; qq < 8; qq++) wq[qq] = wv[qq];
            const float* irow = in_s + (row * 33 + dx) * 32;
#pragma unroll
            for (int px = 0; px < 16; px++) {
                if (bm & (1u << px)) {                // warp-uniform branch
                    const float4* ip = (const float4*)(irow + px * 64);
#pragma unroll
                    for (int qq = 0; qq < 8; qq++) {
                        float4 a = ip[qq];
                        acc[px] = fmaf(a.x, wq[qq].x, acc[px]);
                        acc[px] = fmaf(a.y, wq[qq].y, acc[px]);
                        acc[px] = fmaf(a.z, wq[qq].z, acc[px]);
                        acc[px] = fmaf(a.w, wq[qq].w, acc[px]);
                    }
                }
            }
        }
        float* orow = out + (((size_t)b * Hout + oy) * Hout + ox0) * 32 + co;
#pragma unroll
        for (int px = 0; px < 16; px++) {
            if (sm & (1u << px)) orow[px * 32] = fmaxf(acc[px], 0.0f);
        }
    }
}

// ---------------- masked global pool + MLP head (1024 threads) -------------
__global__ void k_final(
    const float* __restrict__ x2,
    const float* __restrict__ W1, const float* __restrict__ b1,
    const float* __restrict__ W2, const float* __restrict__ b2,
    const float* __restrict__ W3, const float* __restrict__ b3,
    float* __restrict__ out)
{
    __shared__ float s_pool[32][32];
    __shared__ int s_cnt[32];
    __shared__ float s_z[64];
    __shared__ float s_t1[64];

    int b = blockIdx.x;
    int tid = threadIdx.x;
    int wg = tid >> 5;
    int lane = tid & 31;

    float ps = 0.0f;
    int pc = 0;
    const float* y4b = g_y4 + (size_t)b * 4096 * 32;
    const unsigned char* m4b = g_m4 + (size_t)b * 4096;
    for (int p = wg; p < 4096; p += 32) {
        if (m4b[p]) {
            ps += y4b[(size_t)p * 32 + lane];
            pc++;
        }
    }
    s_pool[wg][lane] = ps;
    if (lane == 0) s_cnt[wg] = pc;
    __syncthreads();

    if (tid < 32) {
        float s = 0.0f;
        int c = 0;
#pragma unroll
        for (int w = 0; w < 32; w++) { s += s_pool[w][tid]; c += s_cnt[w]; }
        s_z[tid] = s / fmaxf((float)c, 1.0f);
    }
    if (tid >= 32 && tid < 96) {
        int t = tid - 32;
        float a = b1[t];
        a = fmaf(x2[b * 3 + 0], W1[0 * 64 + t], a);
        a = fmaf(x2[b * 3 + 1], W1[1 * 64 + t], a);
        a = fmaf(x2[b * 3 + 2], W1[2 * 64 + t], a);
        s_t1[t] = fmaxf(a, 0.0f);
    }
    __syncthreads();
    if (tid < 32) {
        float a = b2[tid];
#pragma unroll
        for (int k = 0; k < 64; k++) a = fmaf(s_t1[k], W2[k * 32 + tid], a);
        s_z[32 + tid] = a;
    }
    __syncthreads();
    if (tid < 128) {
        float a = b3[tid];
#pragma unroll
        for (int k = 0; k < 64; k++) a = fmaf(s_z[k], W3[k * 128 + tid], a);
        out[b * 128 + tid] = fmaxf(a, 0.0f);
    }
}

// ---------------- launch: 7 launches; #4 = k_conv_s2<0> (profiled slot) ----
extern "C" void kernel_launch(void* const* d_in, const int* in_sizes, int n_in,
                              void* d_out, int out_size) {
    const int* coords = (const int*)d_in[0];
    const float* feats = (const float*)d_in[1];
    const float* x2 = (const float*)d_in[2];
    const float* K1 = (const float*)d_in[3];
    const float* K2 = (const float*)d_in[4];
    const float* K3 = (const float*)d_in[5];
    const float* K4 = (const float*)d_in[6];
    const float* W1 = (const float*)d_in[7];
    const float* b1 = (const float*)d_in[8];
    const float* W2 = (const float*)d_in[9];
    const float* b2 = (const float*)d_in[10];
    const float* W3 = (const float*)d_in[11];
    const float* b3 = (const float*)d_in[12];
    float* out = (float*)d_out;

    int npts = in_sizes[0] / 3;  // 262144

    cudaFuncSetAttribute(k_conv_s2<0>, cudaFuncAttributeMaxDynamicSharedMemorySize, CONV_SMEM);
    cudaFuncSetAttribute(k_conv_s2<1>, cudaFuncAttributeMaxDynamicSharedMemorySize, CONV_SMEM);
    cudaFuncSetAttribute(k_conv_s2<2>, cudaFuncAttributeMaxDynamicSharedMemorySize, CONV_SMEM);

    k_scatter<<<(npts + 255) / 256, 256>>>(coords, npts);
    k_decode<<<4096, 256>>>(feats);
    k_conv1<<<dim3(32, 16, BB + 1), 256>>>(K1, K2, K3, K4);
    k_conv_s2<0><<<dim3(16, 32, BB), 256, CONV_SMEM>>>();
    k_conv_s2<1><<<dim3(8, 16, BB), 256, CONV_SMEM>>>();
    k_conv_s2<2><<<dim3(4, 8, BB), 256, CONV_SMEM>>>();
    k_final<<<BB, 1024>>>(x2, W1, b1, W2, b2, W3, b3, out);
}

// round 10
// speedup vs baseline: 3.9955x; 1.1024x over previous
#include <cuda_runtime.h>
#include <cstdint>

#define BB 8
#define GSZ 512
#define CC 32

// RULE: g_* symbols are referenced ONLY inside device code (host-shadow bug, R1-R4).
__device__ __align__(16) unsigned g_key[BB * GSZ * GSZ];            // 8 MB
__device__ __align__(16) float g_grid[BB * GSZ * GSZ];
__device__ __align__(16) unsigned char g_m1[BB * GSZ * GSZ];
__device__ __align__(16) unsigned char g_m2[BB * 256 * 256];
__device__ __align__(16) unsigned char g_m3[BB * 128 * 128];
__device__ __align__(16) unsigned char g_m4[BB * 64 * 64];
__device__ __align__(16) float g_y1[(size_t)BB * GSZ * GSZ * CC];
__device__ __align__(16) float g_y2[(size_t)BB * 256 * 256 * CC];
__device__ __align__(16) float g_y3[(size_t)BB * 128 * 128 * CC];
__device__ __align__(16) float g_y4[(size_t)BB * 64 * 64 * CC];
__device__ __align__(16) float g_wt[3 * 9 * 32 * 36];               // pre-transposed weights

// ---------------- scatter: LAST-write-wins, key-only 32-bit atomics --------
__global__ void k_scatter(const int* __restrict__ coords, int n) {
    int i = blockIdx.x * blockDim.x + threadIdx.x;
    if (i >= n) return;
    int b = __ldg(&coords[3 * i + 0]);
    int y = __ldg(&coords[3 * i + 1]);
    int x = __ldg(&coords[3 * i + 2]);
    atomicMax(&g_key[((size_t)b * GSZ + y) * GSZ + x], (unsigned)(i + 1));
}

// ---------------- decode: key -> mask + gathered feat; self-clearing -------
__global__ void k_decode(const float* __restrict__ feats) {
    int n = BB * GSZ * GSZ;
    for (int i = blockIdx.x * blockDim.x + threadIdx.x; i < n; i += gridDim.x * blockDim.x) {
        unsigned v = g_key[i];
        g_m1[i] = v ? (unsigned char)1 : (unsigned char)0;
        g_grid[i] = v ? __ldg(&feats[v - 1]) : 0.0f;
        if (v) g_key[i] = 0;                     // conditional clear (sparse writes)
    }
}

// ---------------- conv1 (16x32 tiles) + fused aux (maskall / wtrans) -------
__global__ void k_conv1(const float* __restrict__ K1, const float* __restrict__ K2,
                        const float* __restrict__ K3, const float* __restrict__ K4) {
    if (blockIdx.z == BB) {
        int bid = blockIdx.y * 32 + blockIdx.x;
        if (bid < 128) {
            int i = bid * 256 + threadIdx.x;
            int X = i & 63;
            int Y = (i >> 6) & 63;
            int b = i >> 12;
            const unsigned char* m1b = g_m1 + ((size_t)b * GSZ + 8 * Y) * GSZ + 8 * X;
            unsigned m2row[4];
            unsigned allor = 0;
#pragma unroll
            for (int r2 = 0; r2 < 4; r2++) {
                uint2 a = *(const uint2*)(m1b + (2 * r2) * GSZ);
                uint2 c = *(const uint2*)(m1b + (2 * r2 + 1) * GSZ);
                unsigned u = a.x | c.x;
                unsigned v = a.y | c.y;
                unsigned tu = u | (u >> 8);
                unsigned tv = v | (v >> 8);
                unsigned res = (tu & 0xFFu) | (((tu >> 16) & 0xFFu) << 8) |
                               ((tv & 0xFFu) << 16) | (((tv >> 16) & 0xFFu) << 24);
                m2row[r2] = res;
                allor |= res;
                *(unsigned*)(g_m2 + ((size_t)b * 256 + 4 * Y + r2) * 256 + 4 * X) = res;
            }
#pragma unroll
            for (int r3 = 0; r3 < 2; r3++) {
                unsigned w = m2row[2 * r3] | m2row[2 * r3 + 1];
                unsigned s = w | (w >> 8);
                unsigned short m3v = (unsigned short)((s & 0xFFu) | (((s >> 16) & 0xFFu) << 8));
                *(unsigned short*)(g_m3 + ((size_t)b * 128 + 2 * Y + r3) * 128 + 2 * X) = m3v;
            }
            unsigned o = allor;
            o |= o >> 16;
            o |= o >> 8;
            g_m4[((size_t)b * 64 + Y) * 64 + X] = (unsigned char)(o & 1u);
        } else if (bid < 131) {
            int L = bid - 128;
            const float* src = (L == 0) ? K2 : (L == 1) ? K3 : K4;
            float* dst = g_wt + L * 10368;
            for (int i = threadIdx.x; i < 9216; i += 256) {
                int t = i >> 10;
                int rem = i & 1023;
                int ci = rem >> 5;
                int co = rem & 31;
                dst[(t * 32 + co) * 36 + ci] = __ldg(&src[i]);
            }
        }
        return;
    }

    __shared__ float in_s[36 * 20];
    __shared__ unsigned omask[32];

    int tid = threadIdx.x;
    int b = blockIdx.z;
    int ox0 = blockIdx.x * 16;
    int oy0 = blockIdx.y * 32;
    int co = tid & 31;
    int wid = tid >> 5;

    float w[25];
#pragma unroll
    for (int t = 0; t < 25; t++) w[t] = __ldg(&K1[t * 32 + co]);

    for (int p = tid; p < 720; p += 256) {
        int r = p / 20;
        int c = p - r * 20;
        int gy = oy0 + r - 2;
        int gx = ox0 + c - 2;
        float v = 0.0f;
        if ((unsigned)gy < (unsigned)GSZ && (unsigned)gx < (unsigned)GSZ)
            v = g_grid[((size_t)b * GSZ + gy) * GSZ + gx];
        in_s[p] = v;
    }
    if (tid < 32) {
        uint4 m = __ldg((const uint4*)(g_m1 + ((size_t)b * GSZ + oy0 + tid) * GSZ + ox0));
        unsigned wv[4] = {m.x, m.y, m.z, m.w};
        unsigned bits = 0;
#pragma unroll
        for (int j = 0; j < 4; j++)
#pragma unroll
            for (int k = 0; k < 4; k++)
                if ((wv[j] >> (8 * k)) & 0xFFu) bits |= 1u << (j * 4 + k);
        omask[tid] = bits;
    }
    __syncthreads();

#pragma unroll
    for (int rr = 0; rr < 4; rr++) {
        int py = wid + rr * 8;
        unsigned bm = omask[py];
        float* orow = g_y1 + (((size_t)b * GSZ + oy0 + py) * GSZ + ox0) * 32 + co;
        while (bm) {
            int px = __ffs(bm) - 1;
            bm &= bm - 1;
            float acc = 0.0f;
#pragma unroll
            for (int t = 0; t < 25; t++) {
                int dy = t / 5;
                int dx = t - dy * 5;
                acc = fmaf(in_s[(py + dy) * 20 + px + dx], w[t], acc);
            }
            orow[px * 32] = fmaxf(acc, 0.0f);
        }
    }
}

// ---------------- SPARSE 3x3 stride-2 pad-1 conv, 32->32 ch ----------------
// Tile 8(x) x 8(y); 37KB smem; weights via __ldg (L2-resident); 4 blocks/SM.
#define C2_INS (289 * 32)                    // 17*17 cells x 32 ch floats
#define C2_SMEM (C2_INS * 4 + 17 * 20 + 2 + 289 * 2 + 16)

template <int L>
__global__ __launch_bounds__(256, 4) void k_conv_s2() {
    const float* in = (L == 0) ? g_y1 : (L == 1) ? g_y2 : g_y3;
    float* out = (L == 0) ? g_y2 : (L == 1) ? g_y3 : g_y4;
    const unsigned char* mi = (L == 0) ? g_m1 : (L == 1) ? g_m2 : g_m3;
    const unsigned char* mo = (L == 0) ? g_m2 : (L == 1) ? g_m3 : g_m4;
    const int Hin = (L == 0) ? 512 : (L == 1) ? 256 : 128;
    const int Hout = Hin / 2;

    extern __shared__ float smem[];
    float* in_s = smem;                                        // [289][32]
    unsigned char* m_s = (unsigned char*)(smem + C2_INS);      // [17][20]
    unsigned short* s_cell = (unsigned short*)(m_s + 17 * 20 + 2);  // [289]
    __shared__ int s_nact;

    int tid = threadIdx.x;
    int lane = tid & 31;
    int b = blockIdx.z;
    int ox0 = blockIdx.x * 8;
    int oy0 = blockIdx.y * 8;
    int ix0 = 2 * ox0 - 1;
    int iy0 = 2 * oy0 - 1;

    const float* in_b = in + (size_t)b * Hin * Hin * 32;
    const unsigned char* mi_b = mi + (size_t)b * Hin * Hin;

    if (tid == 0) s_nact = 0;
    __syncthreads();

    // Phase A: mask scan (289 cells) + warp-aggregated compaction
#pragma unroll
    for (int it = 0; it < 2; it++) {
        int p = tid + it * 256;
        bool valid = p < 289;
        unsigned char mv = 0;
        if (valid) {
            int r = p / 17;
            int c = p - r * 17;
            int gy = iy0 + r;
            int gx = ix0 + c;
            if ((unsigned)gy < (unsigned)Hin && (unsigned)gx < (unsigned)Hin)
                mv = mi_b[gy * Hin + gx];
            m_s[r * 20 + c] = mv;
        }
        unsigned vote = __ballot_sync(0xFFFFFFFFu, valid && mv);
        int base = 0;
        if (lane == 0 && vote) base = atomicAdd(&s_nact, __popc(vote));
        base = __shfl_sync(0xFFFFFFFFu, base, 0);
        if (valid && mv) {
            int pos = base + __popc(vote & ((1u << lane) - 1));
            s_cell[pos] = (unsigned short)p;
        }
    }
    __syncthreads();

    // Phase B: flat copy of active cells only (MLP-friendly)
    int nact = s_nact;
    for (int i = tid; i < nact * 8; i += 256) {
        int k = i >> 3;
        int q = i & 7;
        int cell = s_cell[k];
        int r = cell / 17;
        int c = cell - r * 17;
        int gy = iy0 + r;
        int gx = ix0 + c;
        float4 v = __ldg((const float4*)(in_b + (size_t)(gy * Hin + gx) * 32) + q);
        ((float4*)(in_s + cell * 32))[q] = v;
    }
    __syncthreads();

    int py = tid >> 5;
    int co = tid & 31;
    int oy = oy0 + py;
    unsigned sm = __ballot_sync(0xFFFFFFFFu,
        (co < 8) && mo[((size_t)b * Hout + oy) * Hout + ox0 + (co & 7)]);

    if (sm) {
        float acc[8];
#pragma unroll
        for (int i = 0; i < 8; i++) acc[i] = 0.0f;
        const float* wbase = g_wt + L * 10368;

#pragma unroll 1
        for (int t = 0; t < 9; t++) {
            int dy = t / 3;
            int dx = t - dy * 3;
            int row = 2 * py + dy;
            unsigned bm = __ballot_sync(0xFFFFFFFFu,
                (co < 8) && m_s[row * 20 + 2 * (co & 7) + dx]);
            bm &= sm;
            if (!bm) continue;
            float4 wq[8];
            const float4* wv = (const float4*)(wbase + (t * 32 + co) * 36);
#pragma unroll
            for (int qq = 0; qq < 8; qq++) wq[qq] = __ldg(wv + qq);
            const float* irow = in_s + (row * 17 + dx) * 32;
#pragma unroll
            for (int px = 0; px < 8; px++) {
                if (bm & (1u << px)) {                // warp-uniform branch
                    const float4* ip = (const float4*)(irow + px * 64);
#pragma unroll
                    for (int qq = 0; qq < 8; qq++) {
                        float4 a = ip[qq];
                        acc[px] = fmaf(a.x, wq[qq].x, acc[px]);
                        acc[px] = fmaf(a.y, wq[qq].y, acc[px]);
                        acc[px] = fmaf(a.z, wq[qq].z, acc[px]);
                        acc[px] = fmaf(a.w, wq[qq].w, acc[px]);
                    }
                }
            }
        }
        float* orow = out + (((size_t)b * Hout + oy) * Hout + ox0) * 32 + co;
#pragma unroll
        for (int px = 0; px < 8; px++) {
            if (sm & (1u << px)) orow[px * 32] = fmaxf(acc[px], 0.0f);
        }
    }
}

// ---------------- masked global pool + MLP head (1024 threads) -------------
__global__ void k_final(
    const float* __restrict__ x2,
    const float* __restrict__ W1, const float* __restrict__ b1,
    const float* __restrict__ W2, const float* __restrict__ b2,
    const float* __restrict__ W3, const float* __restrict__ b3,
    float* __restrict__ out)
{
    __shared__ float s_pool[32][32];
    __shared__ int s_cnt[32];
    __shared__ float s_z[64];
    __shared__ float s_t1[64];

    int b = blockIdx.x;
    int tid = threadIdx.x;
    int wg = tid >> 5;
    int lane = tid & 31;

    float ps = 0.0f;
    int pc = 0;
    const float* y4b = g_y4 + (size_t)b * 4096 * 32;
    const unsigned char* m4b = g_m4 + (size_t)b * 4096;
    for (int p = wg; p < 4096; p += 32) {
        if (m4b[p]) {
            ps += y4b[(size_t)p * 32 + lane];
            pc++;
        }
    }
    s_pool[wg][lane] = ps;
    if (lane == 0) s_cnt[wg] = pc;
    __syncthreads();

    if (tid < 32) {
        float s = 0.0f;
        int c = 0;
#pragma unroll
        for (int w = 0; w < 32; w++) { s += s_pool[w][tid]; c += s_cnt[w]; }
        s_z[tid] = s / fmaxf((float)c, 1.0f);
    }
    if (tid >= 32 && tid < 96) {
        int t = tid - 32;
        float a = b1[t];
        a = fmaf(x2[b * 3 + 0], W1[0 * 64 + t], a);
        a = fmaf(x2[b * 3 + 1], W1[1 * 64 + t], a);
        a = fmaf(x2[b * 3 + 2], W1[2 * 64 + t], a);
        s_t1[t] = fmaxf(a, 0.0f);
    }
    __syncthreads();
    if (tid < 32) {
        float a = b2[tid];
#pragma unroll
        for (int k = 0; k < 64; k++) a = fmaf(s_t1[k], W2[k * 32 + tid], a);
        s_z[32 + tid] = a;
    }
    __syncthreads();
    if (tid < 128) {
        float a = b3[tid];
#pragma unroll
        for (int k = 0; k < 64; k++) a = fmaf(s_z[k], W3[k * 128 + tid], a);
        out[b * 128 + tid] = fmaxf(a, 0.0f);
    }
}

// ---------------- launch: #4 = k_conv_s2<0> (profiled slot) ----------------
extern "C" void kernel_launch(void* const* d_in, const int* in_sizes, int n_in,
                              void* d_out, int out_size) {
    const int* coords = (const int*)d_in[0];
    const float* feats = (const float*)d_in[1];
    const float* x2 = (const float*)d_in[2];
    const float* K1 = (const float*)d_in[3];
    const float* K2 = (const float*)d_in[4];
    const float* K3 = (const float*)d_in[5];
    const float* K4 = (const float*)d_in[6];
    const float* W1 = (const float*)d_in[7];
    const float* b1 = (const float*)d_in[8];
    const float* W2 = (const float*)d_in[9];
    const float* b2 = (const float*)d_in[10];
    const float* W3 = (const float*)d_in[11];
    const float* b3 = (const float*)d_in[12];
    float* out = (float*)d_out;

    int npts = in_sizes[0] / 3;  // 262144

    cudaFuncSetAttribute(k_conv_s2<0>, cudaFuncAttributeMaxDynamicSharedMemorySize, C2_SMEM);
    cudaFuncSetAttribute(k_conv_s2<1>, cudaFuncAttributeMaxDynamicSharedMemorySize, C2_SMEM);
    cudaFuncSetAttribute(k_conv_s2<2>, cudaFuncAttributeMaxDynamicSharedMemorySize, C2_SMEM);

    k_scatter<<<(npts + 255) / 256, 256>>>(coords, npts);
    k_decode<<<4096, 256>>>(feats);
    k_conv1<<<dim3(32, 16, BB + 1), 256>>>(K1, K2, K3, K4);
    k_conv_s2<0><<<dim3(32, 32, BB), 256, C2_SMEM>>>();
    k_conv_s2<1><<<dim3(16, 16, BB), 256, C2_SMEM>>>();
    k_conv_s2<2><<<dim3(8, 8, BB), 256, C2_SMEM>>>();
    k_final<<<BB, 1024>>>(x2, W1, b1, W2, b2, W3, b3, out);
}

// round 11
// speedup vs baseline: 4.3656x; 1.0926x over previous
#include <cuda_runtime.h>
#include <cstdint>

#define BB 8
#define GSZ 512
#define CC 32

// RULE: g_* symbols are referenced ONLY inside device code (host-shadow bug, R1-R4).
__device__ __align__(16) unsigned g_key[BB * GSZ * GSZ];            // 8 MB
__device__ __align__(16) float g_grid[BB * GSZ * GSZ];
__device__ __align__(16) unsigned char g_m1[BB * GSZ * GSZ];
__device__ __align__(16) unsigned char g_m2[BB * 256 * 256];
__device__ __align__(16) unsigned char g_m3[BB * 128 * 128];
__device__ __align__(16) unsigned char g_m4[BB * 64 * 64];
__device__ __align__(16) float g_y1[(size_t)BB * GSZ * GSZ * CC];
__device__ __align__(16) float g_y2[(size_t)BB * 256 * 256 * CC];
__device__ __align__(16) float g_y3[(size_t)BB * 128 * 128 * CC];
__device__ __align__(16) float g_y4[(size_t)BB * 64 * 64 * CC];
// weights, coalesced layout: [L][t][qq][co][4] ; lane co reads float4 #(t*8+qq)*32+co
__device__ __align__(16) float g_wt[3 * 9 * 8 * 32 * 4];

// ---------------- scatter: LAST-write-wins, key-only 32-bit atomics --------
__global__ void k_scatter(const int* __restrict__ coords, int n) {
    int i = blockIdx.x * blockDim.x + threadIdx.x;
    if (i >= n) return;
    int b = __ldg(&coords[3 * i + 0]);
    int y = __ldg(&coords[3 * i + 1]);
    int x = __ldg(&coords[3 * i + 2]);
    atomicMax(&g_key[((size_t)b * GSZ + y) * GSZ + x], (unsigned)(i + 1));
}

// ---------------- decode: key -> mask + gathered feat; self-clearing -------
__global__ void k_decode(const float* __restrict__ feats) {
    int n = BB * GSZ * GSZ;
    for (int i = blockIdx.x * blockDim.x + threadIdx.x; i < n; i += gridDim.x * blockDim.x) {
        unsigned v = g_key[i];
        g_m1[i] = v ? (unsigned char)1 : (unsigned char)0;
        g_grid[i] = v ? __ldg(&feats[v - 1]) : 0.0f;
        if (v) g_key[i] = 0;                     // conditional clear (sparse writes)
    }
}

// ---------------- conv1 (16x32 tiles) + fused aux (maskall / wtrans) -------
__global__ void k_conv1(const float* __restrict__ K1, const float* __restrict__ K2,
                        const float* __restrict__ K3, const float* __restrict__ K4) {
    if (blockIdx.z == BB) {
        int bid = blockIdx.y * 32 + blockIdx.x;
        if (bid < 128) {
            int i = bid * 256 + threadIdx.x;
            int X = i & 63;
            int Y = (i >> 6) & 63;
            int b = i >> 12;
            const unsigned char* m1b = g_m1 + ((size_t)b * GSZ + 8 * Y) * GSZ + 8 * X;
            unsigned m2row[4];
            unsigned allor = 0;
#pragma unroll
            for (int r2 = 0; r2 < 4; r2++) {
                uint2 a = *(const uint2*)(m1b + (2 * r2) * GSZ);
                uint2 c = *(const uint2*)(m1b + (2 * r2 + 1) * GSZ);
                unsigned u = a.x | c.x;
                unsigned v = a.y | c.y;
                unsigned tu = u | (u >> 8);
                unsigned tv = v | (v >> 8);
                unsigned res = (tu & 0xFFu) | (((tu >> 16) & 0xFFu) << 8) |
                               ((tv & 0xFFu) << 16) | (((tv >> 16) & 0xFFu) << 24);
                m2row[r2] = res;
                allor |= res;
                *(unsigned*)(g_m2 + ((size_t)b * 256 + 4 * Y + r2) * 256 + 4 * X) = res;
            }
#pragma unroll
            for (int r3 = 0; r3 < 2; r3++) {
                unsigned w = m2row[2 * r3] | m2row[2 * r3 + 1];
                unsigned s = w | (w >> 8);
                unsigned short m3v = (unsigned short)((s & 0xFFu) | (((s >> 16) & 0xFFu) << 8));
                *(unsigned short*)(g_m3 + ((size_t)b * 128 + 2 * Y + r3) * 128 + 2 * X) = m3v;
            }
            unsigned o = allor;
            o |= o >> 16;
            o |= o >> 8;
            g_m4[((size_t)b * 64 + Y) * 64 + X] = (unsigned char)(o & 1u);
        } else if (bid < 131) {
            int L = bid - 128;
            const float* src = (L == 0) ? K2 : (L == 1) ? K3 : K4;
            float* dst = g_wt + L * 9216;
            // dst[((t*8+qq)*32+co)*4 + j] = src[(t*32 + qq*4 + j)*32 + co]
            for (int i = threadIdx.x; i < 9216; i += 256) {
                int t = i >> 10;
                int rem = i & 1023;
                int ci = rem >> 5;          // 0..31
                int co = rem & 31;
                int qq = ci >> 2;
                int j = ci & 3;
                dst[((t * 8 + qq) * 32 + co) * 4 + j] = __ldg(&src[i]);
            }
        }
        return;
    }

    __shared__ float in_s[36 * 20];
    __shared__ unsigned omask[32];

    int tid = threadIdx.x;
    int b = blockIdx.z;
    int ox0 = blockIdx.x * 16;
    int oy0 = blockIdx.y * 32;
    int co = tid & 31;
    int wid = tid >> 5;

    float w[25];
#pragma unroll
    for (int t = 0; t < 25; t++) w[t] = __ldg(&K1[t * 32 + co]);

    for (int p = tid; p < 720; p += 256) {
        int r = p / 20;
        int c = p - r * 20;
        int gy = oy0 + r - 2;
        int gx = ox0 + c - 2;
        float v = 0.0f;
        if ((unsigned)gy < (unsigned)GSZ && (unsigned)gx < (unsigned)GSZ)
            v = g_grid[((size_t)b * GSZ + gy) * GSZ + gx];
        in_s[p] = v;
    }
    if (tid < 32) {
        uint4 m = __ldg((const uint4*)(g_m1 + ((size_t)b * GSZ + oy0 + tid) * GSZ + ox0));
        unsigned wv[4] = {m.x, m.y, m.z, m.w};
        unsigned bits = 0;
#pragma unroll
        for (int j = 0; j < 4; j++)
#pragma unroll
            for (int k = 0; k < 4; k++)
                if ((wv[j] >> (8 * k)) & 0xFFu) bits |= 1u << (j * 4 + k);
        omask[tid] = bits;
    }
    __syncthreads();

#pragma unroll
    for (int rr = 0; rr < 4; rr++) {
        int py = wid + rr * 8;
        unsigned bm = omask[py];
        float* orow = g_y1 + (((size_t)b * GSZ + oy0 + py) * GSZ + ox0) * 32 + co;
        while (bm) {
            int px = __ffs(bm) - 1;
            bm &= bm - 1;
            float acc = 0.0f;
#pragma unroll
            for (int t = 0; t < 25; t++) {
                int dy = t / 5;
                int dx = t - dy * 5;
                acc = fmaf(in_s[(py + dy) * 20 + px + dx], w[t], acc);
            }
            orow[px * 32] = fmaxf(acc, 0.0f);
        }
    }
}

// ---------------- SPARSE 3x3 stride-2 pad-1 conv, 32->32 ch ----------------
// Tile 8(x) x 8(y); 37KB smem; coalesced weight LDG; precomputed tap masks.
#define C2_INS (289 * 32)                    // 17*17 cells x 32 ch floats
#define C2_SMEM (C2_INS * 4 + 17 * 20 + 2 + 289 * 2 + 51 + 128)

template <int L>
__global__ __launch_bounds__(256, 4) void k_conv_s2() {
    const float* in = (L == 0) ? g_y1 : (L == 1) ? g_y2 : g_y3;
    float* out = (L == 0) ? g_y2 : (L == 1) ? g_y3 : g_y4;
    const unsigned char* mi = (L == 0) ? g_m1 : (L == 1) ? g_m2 : g_m3;
    const unsigned char* mo = (L == 0) ? g_m2 : (L == 1) ? g_m3 : g_m4;
    const int Hin = (L == 0) ? 512 : (L == 1) ? 256 : 128;
    const int Hout = Hin / 2;

    extern __shared__ float smem[];
    float* in_s = smem;                                        // [289][32]
    unsigned char* m_s = (unsigned char*)(smem + C2_INS);      // [17][20]
    unsigned short* s_cell = (unsigned short*)(m_s + 17 * 20 + 2);  // [289]
    unsigned char* em = (unsigned char*)(s_cell + 289);        // [17][3] tap masks
    __shared__ int s_nact;

    int tid = threadIdx.x;
    int lane = tid & 31;
    int b = blockIdx.z;
    int ox0 = blockIdx.x * 8;
    int oy0 = blockIdx.y * 8;
    int ix0 = 2 * ox0 - 1;
    int iy0 = 2 * oy0 - 1;

    const float* in_b = in + (size_t)b * Hin * Hin * 32;
    const unsigned char* mi_b = mi + (size_t)b * Hin * Hin;

    if (tid == 0) s_nact = 0;
    __syncthreads();

    // Phase A: mask scan (289 cells) + warp-aggregated compaction
#pragma unroll
    for (int it = 0; it < 2; it++) {
        int p = tid + it * 256;
        bool valid = p < 289;
        unsigned char mv = 0;
        if (valid) {
            int r = p / 17;
            int c = p - r * 17;
            int gy = iy0 + r;
            int gx = ix0 + c;
            if ((unsigned)gy < (unsigned)Hin && (unsigned)gx < (unsigned)Hin)
                mv = mi_b[gy * Hin + gx];
            m_s[r * 20 + c] = mv;
        }
        unsigned vote = __ballot_sync(0xFFFFFFFFu, valid && mv);
        int base = 0;
        if (lane == 0 && vote) base = atomicAdd(&s_nact, __popc(vote));
        base = __shfl_sync(0xFFFFFFFFu, base, 0);
        if (valid && mv) {
            int pos = base + __popc(vote & ((1u << lane) - 1));
            s_cell[pos] = (unsigned short)p;
        }
    }
    __syncthreads();

    // Phase A2: per-(row,dx) tap masks: bit px = m_s[row][2*px+dx]
    if (tid < 51) {
        int r = tid / 3;
        int dx = tid - r * 3;
        unsigned bits = 0;
#pragma unroll
        for (int px = 0; px < 8; px++)
            if (m_s[r * 20 + 2 * px + dx]) bits |= 1u << px;
        em[r * 3 + dx] = (unsigned char)bits;
    }

    // Phase B: flat copy of active cells only (MLP-friendly)
    int nact = s_nact;
    for (int i = tid; i < nact * 8; i += 256) {
        int k = i >> 3;
        int q = i & 7;
        int cell = s_cell[k];
        int r = cell / 17;
        int c = cell - r * 17;
        int gy = iy0 + r;
        int gx = ix0 + c;
        float4 v = __ldg((const float4*)(in_b + (size_t)(gy * Hin + gx) * 32) + q);
        ((float4*)(in_s + cell * 32))[q] = v;
    }
    __syncthreads();

    int py = tid >> 5;
    int co = tid & 31;
    int oy = oy0 + py;
    unsigned sm = __ballot_sync(0xFFFFFFFFu,
        (co < 8) && mo[((size_t)b * Hout + oy) * Hout + ox0 + (co & 7)]);

    if (sm) {
        float acc[8];
#pragma unroll
        for (int i = 0; i < 8; i++) acc[i] = 0.0f;
        const float4* wbase4 = (const float4*)(g_wt + L * 9216);

#pragma unroll 1
        for (int t = 0; t < 9; t++) {
            int dy = t / 3;
            int dx = t - dy * 3;
            int row = 2 * py + dy;
            unsigned bm = (unsigned)em[row * 3 + dx] & sm;   // broadcast LDS + AND
            if (!bm) continue;
            float4 wq[8];
#pragma unroll
            for (int qq = 0; qq < 8; qq++)
                wq[qq] = __ldg(wbase4 + (t * 8 + qq) * 32 + co);   // coalesced
            const float* irow = in_s + (row * 17 + dx) * 32;
#pragma unroll
            for (int px = 0; px < 8; px++) {
                if (bm & (1u << px)) {                // warp-uniform branch
                    const float4* ip = (const float4*)(irow + px * 64);
#pragma unroll
                    for (int qq = 0; qq < 8; qq++) {
                        float4 a = ip[qq];
                        acc[px] = fmaf(a.x, wq[qq].x, acc[px]);
                        acc[px] = fmaf(a.y, wq[qq].y, acc[px]);
                        acc[px] = fmaf(a.z, wq[qq].z, acc[px]);
                        acc[px] = fmaf(a.w, wq[qq].w, acc[px]);
                    }
                }
            }
        }
        float* orow = out + (((size_t)b * Hout + oy) * Hout + ox0) * 32 + co;
#pragma unroll
        for (int px = 0; px < 8; px++) {
            if (sm & (1u << px)) orow[px * 32] = fmaxf(acc[px], 0.0f);
        }
    }
}

// ---------------- masked global pool + MLP head (1024 threads) -------------
__global__ void k_final(
    const float* __restrict__ x2,
    const float* __restrict__ W1, const float* __restrict__ b1,
    const float* __restrict__ W2, const float* __restrict__ b2,
    const float* __restrict__ W3, const float* __restrict__ b3,
    float* __restrict__ out)
{
    __shared__ float s_pool[32][32];
    __shared__ int s_cnt[32];
    __shared__ float s_z[64];
    __shared__ float s_t1[64];

    int b = blockIdx.x;
    int tid = threadIdx.x;
    int wg = tid >> 5;
    int lane = tid & 31;

    float ps = 0.0f;
    int pc = 0;
    const float* y4b = g_y4 + (size_t)b * 4096 * 32;
    const unsigned char* m4b = g_m4 + (size_t)b * 4096;
    for (int p = wg; p < 4096; p += 32) {
        if (m4b[p]) {
            ps += y4b[(size_t)p * 32 + lane];
            pc++;
        }
    }
    s_pool[wg][lane] = ps;
    if (lane == 0) s_cnt[wg] = pc;
    __syncthreads();

    if (tid < 32) {
        float s = 0.0f;
        int c = 0;
#pragma unroll
        for (int w = 0; w < 32; w++) { s += s_pool[w][tid]; c += s_cnt[w]; }
        s_z[tid] = s / fmaxf((float)c, 1.0f);
    }
    if (tid >= 32 && tid < 96) {
        int t = tid - 32;
        float a = b1[t];
        a = fmaf(x2[b * 3 + 0], W1[0 * 64 + t], a);
        a = fmaf(x2[b * 3 + 1], W1[1 * 64 + t], a);
        a = fmaf(x2[b * 3 + 2], W1[2 * 64 + t], a);
        s_t1[t] = fmaxf(a, 0.0f);
    }
    __syncthreads();
    if (tid < 32) {
        float a = b2[tid];
#pragma unroll
        for (int k = 0; k < 64; k++) a = fmaf(s_t1[k], W2[k * 32 + tid], a);
        s_z[32 + tid] = a;
    }
    __syncthreads();
    if (tid < 128) {
        float a = b3[tid];
#pragma unroll
        for (int k = 0; k < 64; k++) a = fmaf(s_z[k], W3[k * 128 + tid], a);
        out[b * 128 + tid] = fmaxf(a, 0.0f);
    }
}

// ---------------- launch: #4 = k_conv_s2<0> (profiled slot) ----------------
extern "C" void kernel_launch(void* const* d_in, const int* in_sizes, int n_in,
                              void* d_out, int out_size) {
    const int* coords = (const int*)d_in[0];
    const float* feats = (const float*)d_in[1];
    const float* x2 = (const float*)d_in[2];
    const float* K1 = (const float*)d_in[3];
    const float* K2 = (const float*)d_in[4];
    const float* K3 = (const float*)d_in[5];
    const float* K4 = (const float*)d_in[6];
    const float* W1 = (const float*)d_in[7];
    const float* b1 = (const float*)d_in[8];
    const float* W2 = (const float*)d_in[9];
    const float* b2 = (const float*)d_in[10];
    const float* W3 = (const float*)d_in[11];
    const float* b3 = (const float*)d_in[12];
    float* out = (float*)d_out;

    int npts = in_sizes[0] / 3;  // 262144

    cudaFuncSetAttribute(k_conv_s2<0>, cudaFuncAttributeMaxDynamicSharedMemorySize, C2_SMEM);
    cudaFuncSetAttribute(k_conv_s2<1>, cudaFuncAttributeMaxDynamicSharedMemorySize, C2_SMEM);
    cudaFuncSetAttribute(k_conv_s2<2>, cudaFuncAttributeMaxDynamicSharedMemorySize, C2_SMEM);

    k_scatter<<<(npts + 255) / 256, 256>>>(coords, npts);
    k_decode<<<4096, 256>>>(feats);
    k_conv1<<<dim3(32, 16, BB + 1), 256>>>(K1, K2, K3, K4);
    k_conv_s2<0><<<dim3(32, 32, BB), 256, C2_SMEM>>>();
    k_conv_s2<1><<<dim3(16, 16, BB), 256, C2_SMEM>>>();
    k_conv_s2<2><<<dim3(8, 8, BB), 256, C2_SMEM>>>();
    k_final<<<BB, 1024>>>(x2, W1, b1, W2, b2, W3, b3, out);
}